// round 11
// baseline (speedup 1.0000x reference)
#include <cuda_runtime.h>
#include <cuda_bf16.h>
#include <cstdint>
#include <math.h>

#define NB   32
#define NC   256
#define NS   1024
#define NBS  (NB * NS)     // 32768
#define NCS  (NC * NS)     // 262144

// tcgen05 exists only on arch-specific (a) targets; the harness also compiles
// a compute_103 (non-a) pass, which must still build AND be correct.
#if defined(__CUDA_ARCH__) && (defined(__CUDA_ARCH_FEAT_SM103_ALL) || defined(__CUDA_ARCH_FEAT_SM100_ALL) || defined(__CUDA_ARCH_FEAT_SM101_ALL))
#define HAS_TCGEN05 1
#else
#define HAS_TCGEN05 0
#endif

// ---------------- device scratch (no allocations allowed) ----------------
__device__ float g_ink_b[NBS];                 // 1/||k_b column||
__device__ float g_inq [NBS];                  // 1/||q_grid column||
__device__ float g_inkg[NBS];                  // 1/||k_grid column||
__device__ float g_qgt[(size_t)NB * NS * NC];  // normalized q_grid, [B,S,C]
__device__ float g_kgt[(size_t)NB * NS * NC];  // normalized k_grid, [B,S,C]
__device__ __nv_bfloat16 g_qbt_hi[(size_t)NB * NS * NC];  // raw q_b, [B,S,C]
__device__ __nv_bfloat16 g_qbt_lo[(size_t)NB * NS * NC];
__device__ __nv_bfloat16 g_kbt_hi[(size_t)NB * NS * NC];  // normalized k_b
__device__ __nv_bfloat16 g_kbt_lo[(size_t)NB * NS * NC];
__device__ unsigned long long g_arg[NBS];      // packed (value, ~j) argmax
__device__ int   g_negidx[NB];
__device__ float g_loss;

// ---------------- PTX helpers ----------------
__device__ __forceinline__ uint32_t smem_u32(const void* p) {
    uint32_t a;
    asm("{ .reg .u64 t; cvta.to.shared.u64 t, %1; cvt.u32.u64 %0, t; }"
        : "=r"(a) : "l"(p));
    return a;
}

#if HAS_TCGEN05
__device__ __forceinline__ uint32_t elect_one_pred() {
    uint32_t pred;
    asm volatile("{\n\t.reg .pred p;\n\telect.sync _|p, 0xFFFFFFFF;\n\t"
                 "selp.b32 %0, 1, 0, p;\n\t}" : "=r"(pred));
    return pred;
}
#define TCGEN05_ALLOC(smem_addr, nCols) \
    asm volatile("tcgen05.alloc.cta_group::1.sync.aligned.shared::cta.b32 [%0], %1;" \
        :: "r"((uint32_t)(smem_addr)), "r"((uint32_t)(nCols)) : "memory")
#define TCGEN05_DEALLOC(tmem, nCols) \
    asm volatile("tcgen05.dealloc.cta_group::1.sync.aligned.b32 %0, %1;" \
        :: "r"(tmem), "r"((uint32_t)(nCols)))
#define TCGEN05_RELINQ() \
    asm volatile("tcgen05.relinquish_alloc_permit.cta_group::1.sync.aligned;")
#define TCGEN05_WAIT_LD() asm volatile("tcgen05.wait::ld.sync.aligned;" ::: "memory")
#define TCGEN05_WAIT_ST() asm volatile("tcgen05.wait::st.sync.aligned;" ::: "memory")
#define TCGEN05_FENCE_BEFORE() asm volatile("tcgen05.fence::before_thread_sync;" ::: "memory")
#define TCGEN05_FENCE_AFTER()  asm volatile("tcgen05.fence::after_thread_sync;" ::: "memory")
#define TCGEN05_COMMIT(mbar) \
    asm volatile("tcgen05.commit.cta_group::1.mbarrier::arrive::one.shared::cluster.b64 [%0];" \
        :: "r"((uint32_t)(mbar)) : "memory")
#define FENCE_ASYNC() asm volatile("fence.proxy.async.shared::cta;" ::: "memory")
#define MBARRIER_INIT(mbar, cnt) \
    asm volatile("mbarrier.init.shared.b64 [%0], %1;" \
        :: "r"((uint32_t)(mbar)), "r"((uint32_t)(cnt)) : "memory")
#define MBARRIER_WAIT_PARITY(mbar, par) do { \
    uint32_t _m = (uint32_t)(mbar); uint32_t _p = (uint32_t)(par); uint32_t _d; \
    asm volatile("{\n\t.reg .pred p;\n\t" \
        "mbarrier.try_wait.parity.acquire.cta.shared::cta.b64 p, [%1], %2;\n\t" \
        "selp.b32 %0, 1, 0, p;\n\t}" : "=r"(_d) : "r"(_m), "r"(_p) : "memory"); \
    if (!_d) { \
        asm volatile("{\n\t.reg .pred P1;\n\t" \
            "WL_%=:\n\t" \
            "mbarrier.try_wait.parity.acquire.cta.shared::cta.b64 P1, [%0], %1, 0x989680;\n\t" \
            "@P1 bra.uni WD_%=;\n\tbra.uni WL_%=;\n\tWD_%=:\n\t}" \
            :: "r"(_m), "r"(_p) : "memory"); \
    } } while(0)

// TS-mode bf16 MMA: D(TMEM) += A(TMEM) * B(SMEM desc)^T
__device__ __forceinline__ void mma_f16_ts(uint32_t d_tmem, uint32_t a_tmem,
                                           uint64_t b_desc, uint32_t idesc,
                                           uint32_t enable) {
    asm volatile("{\n\t.reg .pred p;\n\tsetp.ne.u32 p, %4, 0;\n\t"
        "tcgen05.mma.cta_group::1.kind::f16 [%0], [%1], %2, %3, {%5,%5,%5,%5}, p;\n\t}"
        :: "r"(d_tmem), "r"(a_tmem), "l"(b_desc), "r"(idesc), "r"(enable), "r"(0u)
        : "memory");
}
#define TCGEN05_ST_X64(tmem, r) \
    asm volatile("tcgen05.st.sync.aligned.32x32b.x64.b32 [%0], " \
        "{%1,%2,%3,%4,%5,%6,%7,%8,%9,%10,%11,%12,%13,%14,%15,%16," \
        "%17,%18,%19,%20,%21,%22,%23,%24,%25,%26,%27,%28,%29,%30,%31,%32," \
        "%33,%34,%35,%36,%37,%38,%39,%40,%41,%42,%43,%44,%45,%46,%47,%48," \
        "%49,%50,%51,%52,%53,%54,%55,%56,%57,%58,%59,%60,%61,%62,%63,%64};" \
        :: "r"(tmem), \
        "r"((r)[0]),"r"((r)[1]),"r"((r)[2]),"r"((r)[3]),"r"((r)[4]),"r"((r)[5]),"r"((r)[6]),"r"((r)[7]), \
        "r"((r)[8]),"r"((r)[9]),"r"((r)[10]),"r"((r)[11]),"r"((r)[12]),"r"((r)[13]),"r"((r)[14]),"r"((r)[15]), \
        "r"((r)[16]),"r"((r)[17]),"r"((r)[18]),"r"((r)[19]),"r"((r)[20]),"r"((r)[21]),"r"((r)[22]),"r"((r)[23]), \
        "r"((r)[24]),"r"((r)[25]),"r"((r)[26]),"r"((r)[27]),"r"((r)[28]),"r"((r)[29]),"r"((r)[30]),"r"((r)[31]), \
        "r"((r)[32]),"r"((r)[33]),"r"((r)[34]),"r"((r)[35]),"r"((r)[36]),"r"((r)[37]),"r"((r)[38]),"r"((r)[39]), \
        "r"((r)[40]),"r"((r)[41]),"r"((r)[42]),"r"((r)[43]),"r"((r)[44]),"r"((r)[45]),"r"((r)[46]),"r"((r)[47]), \
        "r"((r)[48]),"r"((r)[49]),"r"((r)[50]),"r"((r)[51]),"r"((r)[52]),"r"((r)[53]),"r"((r)[54]),"r"((r)[55]), \
        "r"((r)[56]),"r"((r)[57]),"r"((r)[58]),"r"((r)[59]),"r"((r)[60]),"r"((r)[61]),"r"((r)[62]),"r"((r)[63]) \
        : "memory")
#define TCGEN05_LD_X32(r, tmem) \
    asm volatile("tcgen05.ld.sync.aligned.32x32b.x32.b32 " \
        "{%0,%1,%2,%3,%4,%5,%6,%7,%8,%9,%10,%11,%12,%13,%14,%15," \
        "%16,%17,%18,%19,%20,%21,%22,%23,%24,%25,%26,%27,%28,%29,%30,%31}, [%32];" \
        : "=r"((r)[0]),"=r"((r)[1]),"=r"((r)[2]),"=r"((r)[3]),"=r"((r)[4]),"=r"((r)[5]),"=r"((r)[6]),"=r"((r)[7]), \
          "=r"((r)[8]),"=r"((r)[9]),"=r"((r)[10]),"=r"((r)[11]),"=r"((r)[12]),"=r"((r)[13]),"=r"((r)[14]),"=r"((r)[15]), \
          "=r"((r)[16]),"=r"((r)[17]),"=r"((r)[18]),"=r"((r)[19]),"=r"((r)[20]),"=r"((r)[21]),"=r"((r)[22]),"=r"((r)[23]), \
          "=r"((r)[24]),"=r"((r)[25]),"=r"((r)[26]),"=r"((r)[27]),"=r"((r)[28]),"=r"((r)[29]),"=r"((r)[30]),"=r"((r)[31]) \
        : "r"(tmem))

static constexpr uint64_t SMEM_DESC_BASE_SW128 =
    (uint64_t(2) << 61) | (uint64_t(1) << 46) | (uint64_t(64) << 32) | (uint64_t(1) << 16);
#define MAKE_SMEM_DESC(a) (SMEM_DESC_BASE_SW128 | ((uint64_t)((a) >> 4) & 0x3FFF))
#define SW128(off) ((off) ^ (((off) >> 3) & 0x70))
// idesc: f32 accum, bf16 a/b, N=64, M=128
#define MMA_IDESC 0x8100490u
#endif  // HAS_TCGEN05

// ---------------- Kernel A: column norms + state reset ----------------
__global__ void norms_init_kernel(const float* __restrict__ kb,
                                  const float* __restrict__ qg,
                                  const float* __restrict__ kg) {
    int t = blockIdx.x * blockDim.x + threadIdx.x;   // 0..32767
    int b = t >> 10, s = t & 1023;
    const float* p1 = kb + b * NCS + s;
    const float* p2 = qg + b * NCS + s;
    const float* p3 = kg + b * NCS + s;
    float s1 = 0.f, s2 = 0.f, s3 = 0.f;
#pragma unroll 8
    for (int c = 0; c < NC; c++) {
        float v1 = p1[c * NS], v2 = p2[c * NS], v3 = p3[c * NS];
        s1 += v1 * v1; s2 += v2 * v2; s3 += v3 * v3;
    }
    g_ink_b[t] = 1.0f / fmaxf(sqrtf(s1), 1e-12f);
    g_inq [t]  = 1.0f / fmaxf(sqrtf(s2), 1e-12f);
    g_inkg[t]  = 1.0f / fmaxf(sqrtf(s3), 1e-12f);
    g_arg[t] = 0ull;                 // graph replays: must reset every call
    if (t == 0) g_loss = 0.0f;
}

// ---------------- Kernel B: normalize + transpose ----------------
// t=0: q_grid -> g_qgt (float, *inq)   t=1: k_grid -> g_kgt (float, *inkg)
// t=2: q_b    -> g_qbt hi/lo (raw)     t=3: k_b    -> g_kbt hi/lo (*ink_b)
__global__ void transpose_kernel(const float* __restrict__ qg,
                                 const float* __restrict__ kg,
                                 const float* __restrict__ qb,
                                 const float* __restrict__ kb) {
    __shared__ float tile[32][33];
    int z = blockIdx.z;              // b*4 + t
    int b = z >> 2;
    int t = z & 3;
    const float* in = (t == 0) ? qg : (t == 1) ? kg : (t == 2) ? qb : kb;
    int c0 = blockIdx.y * 32;
    int s0 = blockIdx.x * 32;
    int x = threadIdx.x, y = threadIdx.y;     // (32, 8)
#pragma unroll
    for (int cc = 0; cc < 32; cc += 8)
        tile[y + cc][x] = in[(size_t)b * NCS + (size_t)(c0 + y + cc) * NS + s0 + x];
    __syncthreads();
#pragma unroll
    for (int cc = 0; cc < 32; cc += 8) {
        int s = s0 + y + cc;
        float v = tile[x][y + cc];
        size_t o = ((size_t)b * NS + s) * NC + c0 + x;
        if (t == 0) {
            g_qgt[o] = v * g_inq[b * NS + s];
        } else if (t == 1) {
            g_kgt[o] = v * g_inkg[b * NS + s];
        } else {
            if (t == 3) v *= g_ink_b[b * NS + s];
            __nv_bfloat16 hi = __float2bfloat16_rn(v);
            __nv_bfloat16 lo = __float2bfloat16_rn(v - __bfloat162float(hi));
            if (t == 2) { g_qbt_hi[o] = hi; g_qbt_lo[o] = lo; }
            else        { g_kbt_hi[o] = hi; g_kbt_lo[o] = lo; }
        }
    }
}

// ---------------- Kernel C: GEMM + argmax (tcgen05 or fallback) -----------
__device__ __forceinline__ unsigned long long pack_key(float v, int j) {
    unsigned int u = __float_as_uint(v);
    u = (u & 0x80000000u) ? ~u : (u | 0x80000000u);     // order-preserving
    return ((unsigned long long)u << 32) | (unsigned int)(0xFFFFFFFFu - (unsigned int)j);
}

// SMEM (dynamic, 1024-aligned):
//   B buf k (k=0,1,2) @ k*65536: hi 32KB @ +0, lo 32KB @ +32768
//   ctrl @ 196608
#define SM_BBUF(k)  ((k) * 65536)
#define SM_BLO_OFF  32768
#define SM_PTR   196608
#define SM_MBAR0 196616
#define SM_MBAR1 196624
#define SMEM_SZ (196608 + 1024)

__global__ __launch_bounds__(128, 1)
void mma_argmax_kernel() {
    extern __shared__ char dsm_raw[];
    uint32_t sm0 = smem_u32(dsm_raw);
    uint32_t smb = (sm0 + 1023) & ~1023u;       // 1024-aligned base
    char* base = dsm_raw + (smb - sm0);

    int tid = threadIdx.x;                       // 128 threads
    int wid = tid >> 5, lane = tid & 31;
    int jh = blockIdx.x;                         // j half: 0/1
    int i0 = blockIdx.y * 128;
    int b  = blockIdx.z;

#if HAS_TCGEN05
    if (wid == 0) TCGEN05_ALLOC(smb + SM_PTR, 512);
    if (tid == 0) { MBARRIER_INIT(smb + SM_MBAR0, 1); MBARRIER_INIT(smb + SM_MBAR1, 1); }
    __syncthreads();
    uint32_t tmem;
    asm volatile("ld.shared.b32 %0, [%1];" : "=r"(tmem) : "r"(smb + SM_PTR));
    uint32_t tA_hi = tmem;            // A hi: cols 0..127
    uint32_t tA_lo = tmem + 128;      // A lo: cols 128..255
    uint32_t tD0   = tmem + 256;      // D ping: cols 256..319
    uint32_t tD1   = tmem + 320;      // D pong: cols 320..383

    // ---- A (q tile, 128 rows x 256 bf16) -> TMEM, hi then lo ----
    {
        uint32_t wo = (uint32_t)(wid) << 21;     // ST subpartition offset
        size_t rowoff = ((size_t)b * NS + i0 + tid) * NC;  // bf16 elements
        const uint4* srcs[2] = { (const uint4*)(g_qbt_hi + rowoff),
                                 (const uint4*)(g_qbt_lo + rowoff) };
        uint32_t tdst[2] = { tA_hi, tA_lo };
#pragma unroll
        for (int p = 0; p < 2; p++) {
#pragma unroll
            for (int half = 0; half < 2; half++) {
                uint32_t r[64];
#pragma unroll
                for (int q = 0; q < 16; q++) {
                    uint4 v = srcs[p][half * 16 + q];
                    r[q * 4 + 0] = v.x; r[q * 4 + 1] = v.y;
                    r[q * 4 + 2] = v.z; r[q * 4 + 3] = v.w;
                }
                TCGEN05_ST_X64(tdst[p] + half * 64 + wo, r);
            }
        }
        TCGEN05_WAIT_ST();
    }
    TCGEN05_FENCE_BEFORE();

    // ---- B loader: 64 rows x 512B, SW128 blocked atoms (8 atom-rows) ----
    auto load_B = [&](int chunk, int buf) {
        int jb = jh * 512 + chunk * 64;
        const char* sh = (const char*)(g_kbt_hi + ((size_t)b * NS + jb) * NC);
        const char* sl = (const char*)(g_kbt_lo + ((size_t)b * NS + jb) * NC);
        char* dh = base + SM_BBUF(buf);
        char* dl = dh + SM_BLO_OFF;
#pragma unroll
        for (int it = 0; it < 16; it++) {        // 2048 16B-chunks / 128 thr
            int idx = tid + it * 128;
            int row = idx >> 5;
            int cb  = (idx & 31) * 16;
            uint32_t off = (uint32_t)(((row >> 3) + (cb >> 7) * 8) * 1024
                                      + (row & 7) * 128 + (cb & 127));
            uint32_t sw = SW128(off);
            *(uint4*)(dh + sw) = *(const uint4*)(sh + (size_t)row * 512 + cb);
            *(uint4*)(dl + sw) = *(const uint4*)(sl + (size_t)row * 512 + cb);
        }
    };

    // issue one chunk's 48 MMAs into tDx; commit on that chunk's mbar
    auto issue_chunk = [&](int chunk) {
        int buf = chunk % 3;
        uint32_t tD = (chunk & 1) ? tD1 : tD0;
        uint32_t mb = smb + ((chunk & 1) ? SM_MBAR1 : SM_MBAR0);
        uint64_t bh = MAKE_SMEM_DESC(smb + SM_BBUF(buf));
        uint64_t bl = MAKE_SMEM_DESC(smb + SM_BBUF(buf) + SM_BLO_OFF);
#pragma unroll
        for (int ks = 0; ks < 16; ks++) {
            uint32_t aoff = ks * 8;
            uint64_t boff = (uint64_t)((ks >> 2) * 512 + (ks & 3) * 2);
            mma_f16_ts(tD, tA_hi + aoff, bh + boff, MMA_IDESC, ks != 0);
            mma_f16_ts(tD, tA_hi + aoff, bl + boff, MMA_IDESC, 1u);
            mma_f16_ts(tD, tA_lo + aoff, bh + boff, MMA_IDESC, 1u);
        }
        TCGEN05_COMMIT(mb);
    };

    // preamble: B0, B1 loaded; MMA(0) in flight
    load_B(0, 0);
    load_B(1, 1);
    __syncthreads();
    FENCE_ASYNC();
    if (wid == 0) {
        TCGEN05_FENCE_AFTER();
        if (elect_one_pred()) issue_chunk(0);
    }

    float best = -3.4e38f;
    int   bj   = 0;
    int   jrow_base = jh * 512;

    for (int c = 0; c < 8; c++) {
        // issue next chunk (different D buffer AND different mbarrier than c;
        // mbar[(c+1)&1] was last waited at iter c-1 -> at most 1 phase ahead)
        if (c < 7 && wid == 0) {
            TCGEN05_FENCE_AFTER();
            if (elect_one_pred()) issue_chunk(c + 1);
        }
        // prefetch B for chunk c+2 (its buffer was consumed by chunk c-1,
        // whose completion was observed at iter c-1's wait)
        if (c < 6) load_B(c + 2, (c + 2) % 3);

        // wait for chunk c's MMAs: mbar[c&1], parity flips every 2 chunks
        MBARRIER_WAIT_PARITY(smb + ((c & 1) ? SM_MBAR1 : SM_MBAR0), (c >> 1) & 1);
        TCGEN05_FENCE_AFTER();
        uint32_t tD = (c & 1) ? tD1 : tD0;
#pragma unroll
        for (int g = 0; g < 2; g++) {
            uint32_t regs[32];
            TCGEN05_LD_X32(regs, tD + g * 32);
            TCGEN05_WAIT_LD();
            int j0 = jrow_base + c * 64 + g * 32;
#pragma unroll
            for (int cc = 0; cc < 32; cc++) {    // ascending j -> first-max kept
                float v = __uint_as_float(regs[cc]);
                if (v > best) { best = v; bj = j0 + cc; }
            }
        }
        TCGEN05_FENCE_BEFORE();
        __syncthreads();        // D(c) drained by all warps; B(c+2) stores done
        FENCE_ASYNC();
    }

    int row = i0 + wid * 32 + lane;
    atomicMax(&g_arg[b * NS + row], pack_key(best, bj));

    __syncthreads();
    if (wid == 0) { TCGEN05_RELINQ(); TCGEN05_DEALLOC(tmem, 512); }
#else
    // ---------- fallback (non-a target): smem-cached dot products ----------
    float* As = (float*)base;                    // 128*257*4 = 131584 B
    float* kv = As + 128 * 257;                  // 256 floats
    {
        size_t rowoff = ((size_t)b * NS + i0 + tid) * NC;
        const __nv_bfloat16* h = g_qbt_hi + rowoff;
        const __nv_bfloat16* l = g_qbt_lo + rowoff;
#pragma unroll 8
        for (int c = 0; c < NC; c++)
            As[tid * 257 + c] = __bfloat162float(h[c]) + __bfloat162float(l[c]);
    }
    __syncthreads();

    float best = -3.4e38f;
    int   bj   = 0;
    for (int j = 0; j < 512; j++) {
        int jr = jh * 512 + j;
        size_t ko = ((size_t)b * NS + jr) * NC;
        __syncthreads();                          // protect kv from prev iter
        kv[2 * tid]     = __bfloat162float(g_kbt_hi[ko + 2 * tid])
                        + __bfloat162float(g_kbt_lo[ko + 2 * tid]);
        kv[2 * tid + 1] = __bfloat162float(g_kbt_hi[ko + 2 * tid + 1])
                        + __bfloat162float(g_kbt_lo[ko + 2 * tid + 1]);
        __syncthreads();
        float dot = 0.f;
#pragma unroll 8
        for (int c = 0; c < NC; c++) dot += As[tid * 257 + c] * kv[c];
        if (dot > best) { best = dot; bj = jr; }  // ascending j -> first max
    }
    atomicMax(&g_arg[b * NS + i0 + tid], pack_key(best, bj));
    (void)wid; (void)lane;
#endif
}

// ---------------- Kernel D: jax PARTITIONABLE threefry -> uniform -> neg_idx -
__device__ __forceinline__ void threefry2x32(uint32_t k0, uint32_t k1,
                                             uint32_t x0, uint32_t x1,
                                             uint32_t& o0, uint32_t& o1) {
    uint32_t ks0 = k0, ks1 = k1, ks2 = k0 ^ k1 ^ 0x1BD11BDAu;
    const int r0[4] = {13, 15, 26, 6};
    const int r1[4] = {17, 29, 16, 24};
    x0 += ks0; x1 += ks1;
    uint32_t ks[3] = {ks0, ks1, ks2};
#pragma unroll
    for (int i = 0; i < 5; i++) {
        const int* rr = (i & 1) ? r1 : r0;
#pragma unroll
        for (int j = 0; j < 4; j++) {
            x0 += x1;
            x1 = (x1 << rr[j]) | (x1 >> (32 - rr[j]));
            x1 ^= x0;
        }
        x0 += ks[(i + 1) % 3];
        x1 += ks[(i + 2) % 3] + (uint32_t)(i + 1);
    }
    o0 = x0; o1 = x1;
}

__global__ void negidx_kernel(const int* __restrict__ labels_raw) {
    __shared__ float uf[1024];
    __shared__ int lab[32];
    __shared__ int is64;
    int t = threadIdx.x;   // 1024 threads, one per element of u (32x32)
    uint32_t o0, o1;
    threefry2x32(0u, 42u, 0u, (uint32_t)t, o0, o1);   // counter = (hi=0, lo=n)
    uint32_t bits = o0 ^ o1;                           // partitionable fold
    uf[t] = __uint_as_float((bits >> 9) | 0x3f800000u) - 1.0f;
    if (t == 0) {
        int all0 = 1;
        for (int i = 1; i < 32; i += 2) all0 &= (labels_raw[i] == 0);
        is64 = all0;
    }
    __syncthreads();
    if (t < 32) lab[t] = is64 ? labels_raw[2 * t] : labels_raw[t];
    __syncthreads();
    if (t < 32) {
        int lb = lab[t];
        float best = -2.0f; int bi = 0;
        for (int j = 0; j < 32; j++) {
            float v = (lab[j] != lb) ? uf[t * 32 + j] : -1.0f;
            if (v > best) { best = v; bi = j; }    // first-max ties
        }
        g_negidx[t] = bi;
    }
}

// ---------------- Kernel E: loss terms (warp per (b,i)) ----------------
__global__ void loss_kernel() {
    __shared__ float part[8];
    int wid = threadIdx.x >> 5, lane = threadIdx.x & 31;
    int gw = blockIdx.x * 8 + wid;          // 0..32767
    int b = gw >> 10, i = gw & 1023;
    unsigned long long key = g_arg[gw];
    int idx = (int)(0xFFFFFFFFu - (unsigned int)(key & 0xFFFFFFFFull));
    int nb = g_negidx[b];
    const float4* q  = (const float4*)(g_qgt + (size_t)gw * NC);
    const float4* kp = (const float4*)(g_kgt + ((size_t)b  * NS + idx) * NC);
    const float4* kn = (const float4*)(g_kgt + ((size_t)nb * NS + i)   * NC);
    float dp = 0.f, dn = 0.f;
#pragma unroll
    for (int u = 0; u < 2; u++) {
        int c4 = lane + u * 32;
        float4 qv = q[c4], pv = kp[c4], nv = kn[c4];
        dp += qv.x * pv.x + qv.y * pv.y + qv.z * pv.z + qv.w * pv.w;
        dn += qv.x * nv.x + qv.y * nv.y + qv.z * nv.z + qv.w * nv.w;
    }
#pragma unroll
    for (int off = 16; off; off >>= 1) {
        dp += __shfl_xor_sync(0xFFFFFFFFu, dp, off);
        dn += __shfl_xor_sync(0xFFFFFFFFu, dn, off);
    }
    if (lane == 0) {
        float p = dp * 10.0f;   // / TEMP
        float n = dn * 10.0f;
        part[wid] = logf(expf(p) + expf(n) + 1e-6f) - p;
    }
    __syncthreads();
    if (threadIdx.x == 0) {
        float s = 0.f;
        for (int w = 0; w < 8; w++) s += part[w];
        atomicAdd(&g_loss, s);
    }
}

__global__ void finalize_kernel(float* out) {
    out[0] = g_loss * (1.0f / 32768.0f);   // mean * LAM(=1)
}

// ---------------- entry ----------------
extern "C" void kernel_launch(void* const* d_in, const int* in_sizes, int n_in,
                              void* d_out, int out_size) {
    const float* q_b    = (const float*)d_in[0];
    const float* k_b    = (const float*)d_in[1];
    const float* q_grid = (const float*)d_in[2];
    const float* k_grid = (const float*)d_in[3];
    const int*   labels = (const int*)d_in[4];

    static int smem_set = 0;
    if (!smem_set) {
        cudaFuncSetAttribute(mma_argmax_kernel,
                             cudaFuncAttributeMaxDynamicSharedMemorySize, SMEM_SZ);
        smem_set = 1;
    }

    norms_init_kernel<<<128, 256>>>(k_b, q_grid, k_grid);
    transpose_kernel<<<dim3(32, 8, 128), dim3(32, 8)>>>(q_grid, k_grid, q_b, k_b);
    negidx_kernel<<<1, 1024>>>(labels);
    mma_argmax_kernel<<<dim3(2, 8, 32), 128, SMEM_SZ>>>();
    loss_kernel<<<4096, 256>>>();
    finalize_kernel<<<1, 1>>>((float*)d_out);
}

// round 12
// speedup vs baseline: 1.6874x; 1.6874x over previous
#include <cuda_runtime.h>
#include <cuda_bf16.h>
#include <cstdint>
#include <math.h>

#define NB   32
#define NC   256
#define NS   1024
#define NBS  (NB * NS)     // 32768
#define NCS  (NC * NS)     // 262144

// tcgen05 exists only on arch-specific (a) targets; the harness also compiles
// a compute_103 (non-a) pass, which must still build AND be correct.
#if defined(__CUDA_ARCH__) && (defined(__CUDA_ARCH_FEAT_SM103_ALL) || defined(__CUDA_ARCH_FEAT_SM100_ALL) || defined(__CUDA_ARCH_FEAT_SM101_ALL))
#define HAS_TCGEN05 1
#else
#define HAS_TCGEN05 0
#endif

// ---------------- device scratch (no allocations allowed) ----------------
__device__ float g_qgt[(size_t)NB * NS * NC];  // normalized q_grid, [B,S,C]
__device__ float g_kgt[(size_t)NB * NS * NC];  // normalized k_grid, [B,S,C]
__device__ __nv_bfloat16 g_qbt_hi[(size_t)NB * NS * NC];  // raw q_b, [B,S,C]
__device__ __nv_bfloat16 g_qbt_lo[(size_t)NB * NS * NC];
__device__ __nv_bfloat16 g_kbt_hi[(size_t)NB * NS * NC];  // k_b * 1/||k_b||
__device__ __nv_bfloat16 g_kbt_lo[(size_t)NB * NS * NC];
__device__ unsigned long long g_arg[NBS];      // packed (value, ~j) argmax
__device__ int   g_negidx[NB];
__device__ float g_loss;

// ---------------- PTX helpers ----------------
__device__ __forceinline__ uint32_t smem_u32(const void* p) {
    uint32_t a;
    asm("{ .reg .u64 t; cvta.to.shared.u64 t, %1; cvt.u32.u64 %0, t; }"
        : "=r"(a) : "l"(p));
    return a;
}

#if HAS_TCGEN05
__device__ __forceinline__ uint32_t elect_one_pred() {
    uint32_t pred;
    asm volatile("{\n\t.reg .pred p;\n\telect.sync _|p, 0xFFFFFFFF;\n\t"
                 "selp.b32 %0, 1, 0, p;\n\t}" : "=r"(pred));
    return pred;
}
#define TCGEN05_ALLOC(smem_addr, nCols) \
    asm volatile("tcgen05.alloc.cta_group::1.sync.aligned.shared::cta.b32 [%0], %1;" \
        :: "r"((uint32_t)(smem_addr)), "r"((uint32_t)(nCols)) : "memory")
#define TCGEN05_DEALLOC(tmem, nCols) \
    asm volatile("tcgen05.dealloc.cta_group::1.sync.aligned.b32 %0, %1;" \
        :: "r"(tmem), "r"((uint32_t)(nCols)))
#define TCGEN05_RELINQ() \
    asm volatile("tcgen05.relinquish_alloc_permit.cta_group::1.sync.aligned;")
#define TCGEN05_WAIT_LD() asm volatile("tcgen05.wait::ld.sync.aligned;" ::: "memory")
#define TCGEN05_WAIT_ST() asm volatile("tcgen05.wait::st.sync.aligned;" ::: "memory")
#define TCGEN05_FENCE_BEFORE() asm volatile("tcgen05.fence::before_thread_sync;" ::: "memory")
#define TCGEN05_FENCE_AFTER()  asm volatile("tcgen05.fence::after_thread_sync;" ::: "memory")
#define TCGEN05_COMMIT(mbar) \
    asm volatile("tcgen05.commit.cta_group::1.mbarrier::arrive::one.shared::cluster.b64 [%0];" \
        :: "r"((uint32_t)(mbar)) : "memory")
#define FENCE_ASYNC() asm volatile("fence.proxy.async.shared::cta;" ::: "memory")
#define MBARRIER_INIT(mbar, cnt) \
    asm volatile("mbarrier.init.shared.b64 [%0], %1;" \
        :: "r"((uint32_t)(mbar)), "r"((uint32_t)(cnt)) : "memory")
#define MBARRIER_ARRIVE(mbar) \
    asm volatile("mbarrier.arrive.shared.b64 _, [%0];" \
        :: "r"((uint32_t)(mbar)) : "memory")
#define MBARRIER_WAIT_PARITY(mbar, par) do { \
    uint32_t _m = (uint32_t)(mbar); uint32_t _p = (uint32_t)(par); uint32_t _d; \
    asm volatile("{\n\t.reg .pred p;\n\t" \
        "mbarrier.try_wait.parity.acquire.cta.shared::cta.b64 p, [%1], %2;\n\t" \
        "selp.b32 %0, 1, 0, p;\n\t}" : "=r"(_d) : "r"(_m), "r"(_p) : "memory"); \
    if (!_d) { \
        asm volatile("{\n\t.reg .pred P1;\n\t" \
            "WL_%=:\n\t" \
            "mbarrier.try_wait.parity.acquire.cta.shared::cta.b64 P1, [%0], %1, 0x989680;\n\t" \
            "@P1 bra.uni WD_%=;\n\tbra.uni WL_%=;\n\tWD_%=:\n\t}" \
            :: "r"(_m), "r"(_p) : "memory"); \
    } } while(0)
#define NAMED_BAR(id, n) \
    asm volatile("bar.sync %0, %1;" :: "r"(id), "r"(n) : "memory")

// TS-mode bf16 MMA: D(TMEM) += A(TMEM) * B(SMEM desc)^T
__device__ __forceinline__ void mma_f16_ts(uint32_t d_tmem, uint32_t a_tmem,
                                           uint64_t b_desc, uint32_t idesc,
                                           uint32_t enable) {
    asm volatile("{\n\t.reg .pred p;\n\tsetp.ne.u32 p, %4, 0;\n\t"
        "tcgen05.mma.cta_group::1.kind::f16 [%0], [%1], %2, %3, {%5,%5,%5,%5}, p;\n\t}"
        :: "r"(d_tmem), "r"(a_tmem), "l"(b_desc), "r"(idesc), "r"(enable), "r"(0u)
        : "memory");
}
#define TCGEN05_ST_X32(tmem, r) \
    asm volatile("tcgen05.st.sync.aligned.32x32b.x32.b32 [%0], " \
        "{%1,%2,%3,%4,%5,%6,%7,%8,%9,%10,%11,%12,%13,%14,%15,%16," \
        "%17,%18,%19,%20,%21,%22,%23,%24,%25,%26,%27,%28,%29,%30,%31,%32};" \
        :: "r"(tmem), \
        "r"((r)[0]),"r"((r)[1]),"r"((r)[2]),"r"((r)[3]),"r"((r)[4]),"r"((r)[5]),"r"((r)[6]),"r"((r)[7]), \
        "r"((r)[8]),"r"((r)[9]),"r"((r)[10]),"r"((r)[11]),"r"((r)[12]),"r"((r)[13]),"r"((r)[14]),"r"((r)[15]), \
        "r"((r)[16]),"r"((r)[17]),"r"((r)[18]),"r"((r)[19]),"r"((r)[20]),"r"((r)[21]),"r"((r)[22]),"r"((r)[23]), \
        "r"((r)[24]),"r"((r)[25]),"r"((r)[26]),"r"((r)[27]),"r"((r)[28]),"r"((r)[29]),"r"((r)[30]),"r"((r)[31]) \
        : "memory")
#define TCGEN05_LD_X16(r, tmem) \
    asm volatile("tcgen05.ld.sync.aligned.32x32b.x16.b32 " \
        "{%0,%1,%2,%3,%4,%5,%6,%7,%8,%9,%10,%11,%12,%13,%14,%15}, [%16];" \
        : "=r"((r)[0]),"=r"((r)[1]),"=r"((r)[2]),"=r"((r)[3]), \
          "=r"((r)[4]),"=r"((r)[5]),"=r"((r)[6]),"=r"((r)[7]), \
          "=r"((r)[8]),"=r"((r)[9]),"=r"((r)[10]),"=r"((r)[11]), \
          "=r"((r)[12]),"=r"((r)[13]),"=r"((r)[14]),"=r"((r)[15]) \
        : "r"(tmem))

static constexpr uint64_t SMEM_DESC_BASE_SW128 =
    (uint64_t(2) << 61) | (uint64_t(1) << 46) | (uint64_t(64) << 32) | (uint64_t(1) << 16);
#define MAKE_SMEM_DESC(a) (SMEM_DESC_BASE_SW128 | ((uint64_t)((a) >> 4) & 0x3FFF))
#define SW128(off) ((off) ^ (((off) >> 3) & 0x70))
// idesc: f32 accum, bf16 a/b, N=64, M=128
#define MMA_IDESC 0x8100490u
#endif  // HAS_TCGEN05

// ---------------- Kernel A: fused norms + normalize + transpose ----------
// grid (32 s-tiles, 32 b, 4 tensors), block 256.
// z=0: q_b raw -> qbt hi/lo (+ g_arg/g_loss reset)
// z=1: k_b * 1/||col|| -> kbt hi/lo
// z=2: q_grid * 1/||col|| -> g_qgt (f32)
// z=3: k_grid * 1/||col|| -> g_kgt (f32)
__global__ __launch_bounds__(256, 2)
void prep_kernel(const float* __restrict__ qb, const float* __restrict__ kb,
                 const float* __restrict__ qg, const float* __restrict__ kg) {
    __shared__ float tile[32][257];
    __shared__ float psum[8][32];
    __shared__ float invs[32];
    int z  = blockIdx.z;
    int b  = blockIdx.y;
    int s0 = blockIdx.x * 32;
    const float* in = (z == 0) ? qb : (z == 1) ? kb : (z == 2) ? qg : kg;
    int t = threadIdx.x;
    int w = t >> 5, lane = t & 31;

    // load [c][s] -> tile[s][c]; coalesced over s, conflict-free stores
    const float* src = in + (size_t)b * NCS + s0 + lane;
#pragma unroll
    for (int p = 0; p < 32; p++) {
        int c = p * 8 + w;
        tile[lane][c] = src[(size_t)c * NS];
    }
    __syncthreads();

    if (z != 0) {
        int s = lane, seg = w;
        float acc = 0.f;
#pragma unroll
        for (int i = 0; i < 32; i++) {
            float v = tile[s][seg * 32 + i];
            acc += v * v;
        }
        psum[seg][s] = acc;
        __syncthreads();
        if (t < 32) {
            float tot = 0.f;
#pragma unroll
            for (int g = 0; g < 8; g++) tot += psum[g][t];
            invs[t] = 1.0f / fmaxf(sqrtf(tot), 1e-12f);
        }
        __syncthreads();
    }

    // write transposed: warp w handles s = p*8+w, lanes = c (coalesced)
#pragma unroll
    for (int p = 0; p < 4; p++) {
        int s = p * 8 + w;
        float inv = (z != 0) ? invs[s] : 1.0f;
        size_t o = ((size_t)b * NS + s0 + s) * NC;
        if (z >= 2) {
            float* out = (z == 2) ? g_qgt : g_kgt;
#pragma unroll
            for (int q = 0; q < 8; q++) {
                int c = q * 32 + lane;
                out[o + c] = tile[s][c] * inv;
            }
        } else {
            __nv_bfloat16* oh = (z == 0) ? g_qbt_hi : g_kbt_hi;
            __nv_bfloat16* ol = (z == 0) ? g_qbt_lo : g_kbt_lo;
#pragma unroll
            for (int q = 0; q < 8; q++) {
                int c = q * 32 + lane;
                float v = tile[s][c] * inv;
                __nv_bfloat16 hi = __float2bfloat16_rn(v);
                __nv_bfloat16 lo = __float2bfloat16_rn(v - __bfloat162float(hi));
                oh[o + c] = hi; ol[o + c] = lo;
            }
        }
    }
    if (z == 0 && t < 32) g_arg[b * NS + s0 + t] = 0ull;   // graph replay reset
    if (z == 0 && b == 0 && blockIdx.x == 0 && t == 0) g_loss = 0.f;
}

// ---------------- Kernel C: GEMM + argmax (warp-specialized tcgen05) ------
__device__ __forceinline__ unsigned long long pack_key(float v, int j) {
    unsigned int u = __float_as_uint(v);
    u = (u & 0x80000000u) ? ~u : (u | 0x80000000u);     // order-preserving
    return ((unsigned long long)u << 32) | (unsigned int)(0xFFFFFFFFu - (unsigned int)j);
}

// SMEM (dynamic, 1024-aligned): B stage k (k=0..2) @ k*65536 (hi 32K, lo 32K)
#define SM_BBUF(k)   ((k) * 65536)
#define SM_BLO_OFF   32768
#define SM_PTR       196608
#define SM_FULL(s)   (196624 + (s) * 8)
#define SM_EMPTY(s)  (196648 + (s) * 8)
#define SM_CM(k)     (196672 + (k) * 8)
#define SMEM_SZ      (196608 + 2048)

__global__ __launch_bounds__(256, 1)
void mma_argmax_kernel() {
    extern __shared__ char dsm_raw[];
    uint32_t sm0 = smem_u32(dsm_raw);
    uint32_t smb = (sm0 + 1023) & ~1023u;       // 1024-aligned base
    char* base = dsm_raw + (smb - sm0);

    int tid = threadIdx.x;                       // 256 threads
    int wid = tid >> 5, lane = tid & 31;
    int jh = blockIdx.x;                         // j half: 0/1
    int i0 = blockIdx.y * 128;
    int b  = blockIdx.z;

#if HAS_TCGEN05
    if (wid == 0) TCGEN05_ALLOC(smb + SM_PTR, 512);
    if (tid == 0) {
#pragma unroll
        for (int s = 0; s < 3; s++) {
            MBARRIER_INIT(smb + SM_FULL(s), 128);   // all loader threads
            MBARRIER_INIT(smb + SM_EMPTY(s), 1);    // warp0 lane0
        }
        MBARRIER_INIT(smb + SM_CM(0), 1);
        MBARRIER_INIT(smb + SM_CM(1), 1);
    }
    __syncthreads();                              // only block-wide sync

    if (tid >= 128) {
        // ================= loader warps (4-7) =================
        int t2 = tid - 128;
        for (int c = 0; c < 8; c++) {
            int s = c % 3, u = c / 3;
            MBARRIER_WAIT_PARITY(smb + SM_EMPTY(s), (u & 1) ^ 1);
            int jb = jh * 512 + c * 64;
            const char* sh = (const char*)(g_kbt_hi + ((size_t)b * NS + jb) * NC);
            const char* sl = (const char*)(g_kbt_lo + ((size_t)b * NS + jb) * NC);
            char* dh = base + SM_BBUF(s);
            char* dl = dh + SM_BLO_OFF;
#pragma unroll
            for (int it = 0; it < 16; it++) {     // 2048 16B-chunks / 128 thr
                int idx = t2 + it * 128;
                int row = idx >> 5;
                int cb  = (idx & 31) * 16;
                uint32_t off = (uint32_t)(((row >> 3) + (cb >> 7) * 8) * 1024
                                          + (row & 7) * 128 + (cb & 127));
                uint32_t sw = SW128(off);
                *(uint4*)(dh + sw) = *(const uint4*)(sh + (size_t)row * 512 + cb);
                *(uint4*)(dl + sw) = *(const uint4*)(sl + (size_t)row * 512 + cb);
            }
            FENCE_ASYNC();
            MBARRIER_ARRIVE(smb + SM_FULL(s));
        }
        return;   // loaders exit
    }

    // ================= compute warps (0-3) =================
    uint32_t tmem;
    asm volatile("ld.shared.b32 %0, [%1];" : "=r"(tmem) : "r"(smb + SM_PTR));
    uint32_t tA_hi = tmem;            // A hi: cols 0..127
    uint32_t tA_lo = tmem + 128;      // A lo: cols 128..255
    uint32_t tD0   = tmem + 256;      // D ping
    uint32_t tD1   = tmem + 320;      // D pong

    // ---- A (q tile, 128 rows x 256 bf16) -> TMEM, hi then lo ----
    {
        uint32_t wo = (uint32_t)(wid) << 21;
        size_t rowoff = ((size_t)b * NS + i0 + tid) * NC;
        const uint4* srcs[2] = { (const uint4*)(g_qbt_hi + rowoff),
                                 (const uint4*)(g_qbt_lo + rowoff) };
        uint32_t tdst[2] = { tA_hi, tA_lo };
#pragma unroll
        for (int p = 0; p < 2; p++) {
#pragma unroll
            for (int qtr = 0; qtr < 4; qtr++) {   // 4 x 32-reg stores
                uint32_t r[32];
#pragma unroll
                for (int q = 0; q < 8; q++) {
                    uint4 v = srcs[p][qtr * 8 + q];
                    r[q * 4 + 0] = v.x; r[q * 4 + 1] = v.y;
                    r[q * 4 + 2] = v.z; r[q * 4 + 3] = v.w;
                }
                TCGEN05_ST_X32(tdst[p] + qtr * 32 + wo, r);
            }
        }
        TCGEN05_WAIT_ST();
    }
    TCGEN05_FENCE_BEFORE();
    NAMED_BAR(1, 128);                            // A fully in TMEM

    // issue one chunk's 48 MMAs; commit on cm[chunk&1]
    auto issue_chunk = [&](int chunk) {
        int s = chunk % 3;
        uint32_t tD = (chunk & 1) ? tD1 : tD0;
        uint64_t bh = MAKE_SMEM_DESC(smb + SM_BBUF(s));
        uint64_t bl = MAKE_SMEM_DESC(smb + SM_BBUF(s) + SM_BLO_OFF);
#pragma unroll
        for (int ks = 0; ks < 16; ks++) {
            uint32_t aoff = ks * 8;
            uint64_t boff = (uint64_t)((ks >> 2) * 512 + (ks & 3) * 2);
            mma_f16_ts(tD, tA_hi + aoff, bh + boff, MMA_IDESC, ks != 0);
            mma_f16_ts(tD, tA_hi + aoff, bl + boff, MMA_IDESC, 1u);
            mma_f16_ts(tD, tA_lo + aoff, bh + boff, MMA_IDESC, 1u);
        }
        TCGEN05_COMMIT(smb + SM_CM(chunk & 1));
    };

    // prologue: issue chunk 0 as soon as loaders deliver stage 0
    if (wid == 0) {
        MBARRIER_WAIT_PARITY(smb + SM_FULL(0), 0);
        TCGEN05_FENCE_AFTER();
        if (elect_one_pred()) issue_chunk(0);
    }

    float best = -3.4e38f;
    int   bj   = 0;
    int   jrow_base = jh * 512;

    for (int c = 0; c < 8; c++) {
        // issue chunk c+1 (B full-wait; D(c+1) drained at iter c-1's bar)
        if (c < 7 && wid == 0) {
            int n = c + 1;
            MBARRIER_WAIT_PARITY(smb + SM_FULL(n % 3), (n / 3) & 1);
            TCGEN05_FENCE_AFTER();
            if (elect_one_pred()) issue_chunk(n);
        }
        // wait chunk c complete
        MBARRIER_WAIT_PARITY(smb + SM_CM(c & 1), (c >> 1) & 1);
        TCGEN05_FENCE_AFTER();
        if (wid == 0 && lane == 0) MBARRIER_ARRIVE(smb + SM_EMPTY(c % 3));

        // readout + argmax: 4 groups of 16 cols
        uint32_t tD = (c & 1) ? tD1 : tD0;
#pragma unroll
        for (int g = 0; g < 4; g++) {
            uint32_t r[16];
            TCGEN05_LD_X16(r, tD + g * 16);
            TCGEN05_WAIT_LD();
            float v[16], w[16];
#pragma unroll
            for (int i = 0; i < 16; i++) { v[i] = __uint_as_float(r[i]); w[i] = v[i]; }
#pragma unroll
            for (int off = 8; off; off >>= 1)
#pragma unroll
                for (int i = 0; i < off; i++) w[i] = fmaxf(w[i], w[i + off]);
            float m = w[0];
            int gi = 15;
#pragma unroll
            for (int i = 15; i >= 0; i--) if (v[i] == m) gi = i;   // smallest i
            if (m > best) { best = m; bj = jrow_base + c * 64 + g * 16 + gi; }
        }
        TCGEN05_FENCE_BEFORE();
        NAMED_BAR(1, 128);      // D(c) drained before MMA(c+2) issue
    }

    int row = i0 + wid * 32 + lane;
    atomicMax(&g_arg[b * NS + row], pack_key(best, bj));

    NAMED_BAR(1, 128);
    if (wid == 0) { TCGEN05_RELINQ(); TCGEN05_DEALLOC(tmem, 512); }
#else
    // ---------- fallback (non-a target): smem-cached dot products ----------
    float* As = (float*)base;                    // 128*257*4 = 131584 B
    float* kv = As + 128 * 257;                  // 256 floats
    __syncthreads();
    if (tid < 128) {
        size_t rowoff = ((size_t)b * NS + i0 + tid) * NC;
        const __nv_bfloat16* h = g_qbt_hi + rowoff;
        const __nv_bfloat16* l = g_qbt_lo + rowoff;
#pragma unroll 8
        for (int c = 0; c < NC; c++)
            As[tid * 257 + c] = __bfloat162float(h[c]) + __bfloat162float(l[c]);
    }
    __syncthreads();

    float best = -3.4e38f;
    int   bj   = 0;
    for (int j = 0; j < 512; j++) {
        int jr = jh * 512 + j;
        size_t ko = ((size_t)b * NS + jr) * NC;
        __syncthreads();                          // protect kv from prev iter
        kv[tid] = __bfloat162float(g_kbt_hi[ko + tid])
                + __bfloat162float(g_kbt_lo[ko + tid]);
        __syncthreads();
        if (tid < 128) {
            float dot = 0.f;
#pragma unroll 8
            for (int c = 0; c < NC; c++) dot += As[tid * 257 + c] * kv[c];
            if (dot > best) { best = dot; bj = jr; }  // ascending j
        }
    }
    if (tid < 128)
        atomicMax(&g_arg[b * NS + i0 + tid], pack_key(best, bj));
    (void)wid; (void)lane;
#endif
}

// ---------------- Kernel D: jax PARTITIONABLE threefry -> uniform -> neg_idx -
__device__ __forceinline__ void threefry2x32(uint32_t k0, uint32_t k1,
                                             uint32_t x0, uint32_t x1,
                                             uint32_t& o0, uint32_t& o1) {
    uint32_t ks0 = k0, ks1 = k1, ks2 = k0 ^ k1 ^ 0x1BD11BDAu;
    const int r0[4] = {13, 15, 26, 6};
    const int r1[4] = {17, 29, 16, 24};
    x0 += ks0; x1 += ks1;
    uint32_t ks[3] = {ks0, ks1, ks2};
#pragma unroll
    for (int i = 0; i < 5; i++) {
        const int* rr = (i & 1) ? r1 : r0;
#pragma unroll
        for (int j = 0; j < 4; j++) {
            x0 += x1;
            x1 = (x1 << rr[j]) | (x1 >> (32 - rr[j]));
            x1 ^= x0;
        }
        x0 += ks[(i + 1) % 3];
        x1 += ks[(i + 2) % 3] + (uint32_t)(i + 1);
    }
    o0 = x0; o1 = x1;
}

__global__ void negidx_kernel(const int* __restrict__ labels_raw) {
    __shared__ float uf[1024];
    __shared__ int lab[32];
    __shared__ int is64;
    int t = threadIdx.x;   // 1024 threads, one per element of u (32x32)
    uint32_t o0, o1;
    threefry2x32(0u, 42u, 0u, (uint32_t)t, o0, o1);   // counter = (hi=0, lo=n)
    uint32_t bits = o0 ^ o1;                           // partitionable fold
    uf[t] = __uint_as_float((bits >> 9) | 0x3f800000u) - 1.0f;
    if (t == 0) {
        int all0 = 1;
        for (int i = 1; i < 32; i += 2) all0 &= (labels_raw[i] == 0);
        is64 = all0;
    }
    __syncthreads();
    if (t < 32) lab[t] = is64 ? labels_raw[2 * t] : labels_raw[t];
    __syncthreads();
    if (t < 32) {
        int lb = lab[t];
        float best = -2.0f; int bi = 0;
        for (int j = 0; j < 32; j++) {
            float v = (lab[j] != lb) ? uf[t * 32 + j] : -1.0f;
            if (v > best) { best = v; bi = j; }    // first-max ties
        }
        g_negidx[t] = bi;
    }
}

// ---------------- Kernel E: loss terms (warp per (b,i)) ----------------
__global__ void loss_kernel() {
    __shared__ float part[8];
    int wid = threadIdx.x >> 5, lane = threadIdx.x & 31;
    int gw = blockIdx.x * 8 + wid;          // 0..32767
    int b = gw >> 10, i = gw & 1023;
    unsigned long long key = g_arg[gw];
    int idx = (int)(0xFFFFFFFFu - (unsigned int)(key & 0xFFFFFFFFull));
    int nb = g_negidx[b];
    const float4* q  = (const float4*)(g_qgt + (size_t)gw * NC);
    const float4* kp = (const float4*)(g_kgt + ((size_t)b  * NS + idx) * NC);
    const float4* kn = (const float4*)(g_kgt + ((size_t)nb * NS + i)   * NC);
    float dp = 0.f, dn = 0.f;
#pragma unroll
    for (int u = 0; u < 2; u++) {
        int c4 = lane + u * 32;
        float4 qv = q[c4], pv = kp[c4], nv = kn[c4];
        dp += qv.x * pv.x + qv.y * pv.y + qv.z * pv.z + qv.w * pv.w;
        dn += qv.x * nv.x + qv.y * nv.y + qv.z * nv.z + qv.w * nv.w;
    }
#pragma unroll
    for (int off = 16; off; off >>= 1) {
        dp += __shfl_xor_sync(0xFFFFFFFFu, dp, off);
        dn += __shfl_xor_sync(0xFFFFFFFFu, dn, off);
    }
    if (lane == 0) {
        float p = dp * 10.0f;   // / TEMP
        float n = dn * 10.0f;
        part[wid] = logf(expf(p) + expf(n) + 1e-6f) - p;
    }
    __syncthreads();
    if (threadIdx.x == 0) {
        float s = 0.f;
        for (int w = 0; w < 8; w++) s += part[w];
        atomicAdd(&g_loss, s);
    }
}

__global__ void finalize_kernel(float* out) {
    out[0] = g_loss * (1.0f / 32768.0f);   // mean * LAM(=1)
}

// ---------------- entry ----------------
extern "C" void kernel_launch(void* const* d_in, const int* in_sizes, int n_in,
                              void* d_out, int out_size) {
    const float* q_b    = (const float*)d_in[0];
    const float* k_b    = (const float*)d_in[1];
    const float* q_grid = (const float*)d_in[2];
    const float* k_grid = (const float*)d_in[3];
    const int*   labels = (const int*)d_in[4];

    static int smem_set = 0;
    if (!smem_set) {
        cudaFuncSetAttribute(mma_argmax_kernel,
                             cudaFuncAttributeMaxDynamicSharedMemorySize, SMEM_SZ);
        smem_set = 1;
    }

    prep_kernel<<<dim3(32, 32, 4), 256>>>(q_b, k_b, q_grid, k_grid);
    negidx_kernel<<<1, 1024>>>(labels);
    mma_argmax_kernel<<<dim3(2, 8, 32), 256, SMEM_SZ>>>();
    loss_kernel<<<4096, 256>>>();
    finalize_kernel<<<1, 1>>>((float*)d_out);
}

// round 13
// speedup vs baseline: 1.8495x; 1.0960x over previous
#include <cuda_runtime.h>
#include <cuda_bf16.h>
#include <cstdint>
#include <math.h>

#define NB   32
#define NC   256
#define NS   1024
#define NBS  (NB * NS)     // 32768
#define NCS  (NC * NS)     // 262144

// tcgen05 exists only on arch-specific (a) targets; the harness also compiles
// a compute_103 (non-a) pass, which must still build AND be correct.
#if defined(__CUDA_ARCH__) && (defined(__CUDA_ARCH_FEAT_SM103_ALL) || defined(__CUDA_ARCH_FEAT_SM100_ALL) || defined(__CUDA_ARCH_FEAT_SM101_ALL))
#define HAS_TCGEN05 1
#else
#define HAS_TCGEN05 0
#endif

// ---------------- device scratch (no allocations allowed) ----------------
__device__ float g_qgt[(size_t)NB * NS * NC];  // normalized q_grid, [B,S,C]
__device__ float g_kgt[(size_t)NB * NS * NC];  // normalized k_grid, [B,S,C]
__device__ __nv_bfloat16 g_qbt_hi[(size_t)NB * NS * NC];  // raw q_b, [B,S,C]
__device__ __nv_bfloat16 g_kbt_hi[(size_t)NB * NS * NC];  // k_b * 1/||k_b||
__device__ __nv_bfloat16 g_kbt_lo[(size_t)NB * NS * NC];
__device__ unsigned long long g_arg[NBS];      // packed (value, ~j) argmax
__device__ int   g_negidx[NB];
__device__ float g_loss;

// ---------------- PTX helpers ----------------
__device__ __forceinline__ uint32_t smem_u32(const void* p) {
    uint32_t a;
    asm("{ .reg .u64 t; cvta.to.shared.u64 t, %1; cvt.u32.u64 %0, t; }"
        : "=r"(a) : "l"(p));
    return a;
}

#if HAS_TCGEN05
__device__ __forceinline__ uint32_t elect_one_pred() {
    uint32_t pred;
    asm volatile("{\n\t.reg .pred p;\n\telect.sync _|p, 0xFFFFFFFF;\n\t"
                 "selp.b32 %0, 1, 0, p;\n\t}" : "=r"(pred));
    return pred;
}
#define TCGEN05_ALLOC(smem_addr, nCols) \
    asm volatile("tcgen05.alloc.cta_group::1.sync.aligned.shared::cta.b32 [%0], %1;" \
        :: "r"((uint32_t)(smem_addr)), "r"((uint32_t)(nCols)) : "memory")
#define TCGEN05_DEALLOC(tmem, nCols) \
    asm volatile("tcgen05.dealloc.cta_group::1.sync.aligned.b32 %0, %1;" \
        :: "r"(tmem), "r"((uint32_t)(nCols)))
#define TCGEN05_RELINQ() \
    asm volatile("tcgen05.relinquish_alloc_permit.cta_group::1.sync.aligned;")
#define TCGEN05_WAIT_LD() asm volatile("tcgen05.wait::ld.sync.aligned;" ::: "memory")
#define TCGEN05_WAIT_ST() asm volatile("tcgen05.wait::st.sync.aligned;" ::: "memory")
#define TCGEN05_FENCE_BEFORE() asm volatile("tcgen05.fence::before_thread_sync;" ::: "memory")
#define TCGEN05_FENCE_AFTER()  asm volatile("tcgen05.fence::after_thread_sync;" ::: "memory")
#define TCGEN05_COMMIT(mbar) \
    asm volatile("tcgen05.commit.cta_group::1.mbarrier::arrive::one.shared::cluster.b64 [%0];" \
        :: "r"((uint32_t)(mbar)) : "memory")
#define FENCE_ASYNC() asm volatile("fence.proxy.async.shared::cta;" ::: "memory")
#define MBARRIER_INIT(mbar, cnt) \
    asm volatile("mbarrier.init.shared.b64 [%0], %1;" \
        :: "r"((uint32_t)(mbar)), "r"((uint32_t)(cnt)) : "memory")
#define MBARRIER_ARRIVE(mbar) \
    asm volatile("mbarrier.arrive.shared.b64 _, [%0];" \
        :: "r"((uint32_t)(mbar)) : "memory")
#define MBARRIER_WAIT_PARITY(mbar, par) do { \
    uint32_t _m = (uint32_t)(mbar); uint32_t _p = (uint32_t)(par); uint32_t _d; \
    asm volatile("{\n\t.reg .pred p;\n\t" \
        "mbarrier.try_wait.parity.acquire.cta.shared::cta.b64 p, [%1], %2;\n\t" \
        "selp.b32 %0, 1, 0, p;\n\t}" : "=r"(_d) : "r"(_m), "r"(_p) : "memory"); \
    if (!_d) { \
        asm volatile("{\n\t.reg .pred P1;\n\t" \
            "WL_%=:\n\t" \
            "mbarrier.try_wait.parity.acquire.cta.shared::cta.b64 P1, [%0], %1, 0x989680;\n\t" \
            "@P1 bra.uni WD_%=;\n\tbra.uni WL_%=;\n\tWD_%=:\n\t}" \
            :: "r"(_m), "r"(_p) : "memory"); \
    } } while(0)
#define NAMED_BAR(id, n) \
    asm volatile("bar.sync %0, %1;" :: "r"(id), "r"(n) : "memory")

// TS-mode bf16 MMA: D(TMEM) += A(TMEM) * B(SMEM desc)^T
__device__ __forceinline__ void mma_f16_ts(uint32_t d_tmem, uint32_t a_tmem,
                                           uint64_t b_desc, uint32_t idesc,
                                           uint32_t enable) {
    asm volatile("{\n\t.reg .pred p;\n\tsetp.ne.u32 p, %4, 0;\n\t"
        "tcgen05.mma.cta_group::1.kind::f16 [%0], [%1], %2, %3, {%5,%5,%5,%5}, p;\n\t}"
        :: "r"(d_tmem), "r"(a_tmem), "l"(b_desc), "r"(idesc), "r"(enable), "r"(0u)
        : "memory");
}
#define TCGEN05_ST_X32(tmem, r) \
    asm volatile("tcgen05.st.sync.aligned.32x32b.x32.b32 [%0], " \
        "{%1,%2,%3,%4,%5,%6,%7,%8,%9,%10,%11,%12,%13,%14,%15,%16," \
        "%17,%18,%19,%20,%21,%22,%23,%24,%25,%26,%27,%28,%29,%30,%31,%32};" \
        :: "r"(tmem), \
        "r"((r)[0]),"r"((r)[1]),"r"((r)[2]),"r"((r)[3]),"r"((r)[4]),"r"((r)[5]),"r"((r)[6]),"r"((r)[7]), \
        "r"((r)[8]),"r"((r)[9]),"r"((r)[10]),"r"((r)[11]),"r"((r)[12]),"r"((r)[13]),"r"((r)[14]),"r"((r)[15]), \
        "r"((r)[16]),"r"((r)[17]),"r"((r)[18]),"r"((r)[19]),"r"((r)[20]),"r"((r)[21]),"r"((r)[22]),"r"((r)[23]), \
        "r"((r)[24]),"r"((r)[25]),"r"((r)[26]),"r"((r)[27]),"r"((r)[28]),"r"((r)[29]),"r"((r)[30]),"r"((r)[31]) \
        : "memory")
#define TCGEN05_LD_X16(r, tmem) \
    asm volatile("tcgen05.ld.sync.aligned.32x32b.x16.b32 " \
        "{%0,%1,%2,%3,%4,%5,%6,%7,%8,%9,%10,%11,%12,%13,%14,%15}, [%16];" \
        : "=r"((r)[0]),"=r"((r)[1]),"=r"((r)[2]),"=r"((r)[3]), \
          "=r"((r)[4]),"=r"((r)[5]),"=r"((r)[6]),"=r"((r)[7]), \
          "=r"((r)[8]),"=r"((r)[9]),"=r"((r)[10]),"=r"((r)[11]), \
          "=r"((r)[12]),"=r"((r)[13]),"=r"((r)[14]),"=r"((r)[15]) \
        : "r"(tmem))

static constexpr uint64_t SMEM_DESC_BASE_SW128 =
    (uint64_t(2) << 61) | (uint64_t(1) << 46) | (uint64_t(64) << 32) | (uint64_t(1) << 16);
#define MAKE_SMEM_DESC(a) (SMEM_DESC_BASE_SW128 | ((uint64_t)((a) >> 4) & 0x3FFF))
#define SW128(off) ((off) ^ (((off) >> 3) & 0x70))
// idesc: f32 accum, bf16 a/b, N=64, M=128
#define MMA_IDESC 0x8100490u
#endif  // HAS_TCGEN05

// ---------------- Kernel A: fused norms + normalize + transpose ----------
// grid (32 s-tiles, 32 b, 4 tensors), block 256.
// z=0: q_b raw -> qbt hi only (+ g_arg/g_loss reset)
// z=1: k_b * 1/||col|| -> kbt hi/lo
// z=2: q_grid * 1/||col|| -> g_qgt (f32)
// z=3: k_grid * 1/||col|| -> g_kgt (f32)
__global__ __launch_bounds__(256, 2)
void prep_kernel(const float* __restrict__ qb, const float* __restrict__ kb,
                 const float* __restrict__ qg, const float* __restrict__ kg) {
    __shared__ float tile[32][257];
    __shared__ float psum[8][32];
    __shared__ float invs[32];
    int z  = blockIdx.z;
    int b  = blockIdx.y;
    int s0 = blockIdx.x * 32;
    const float* in = (z == 0) ? qb : (z == 1) ? kb : (z == 2) ? qg : kg;
    int t = threadIdx.x;
    int w = t >> 5, lane = t & 31;

    // load [c][s] -> tile[s][c]; coalesced over s, conflict-free stores
    const float* src = in + (size_t)b * NCS + s0 + lane;
#pragma unroll
    for (int p = 0; p < 32; p++) {
        int c = p * 8 + w;
        tile[lane][c] = src[(size_t)c * NS];
    }
    __syncthreads();

    if (z != 0) {
        int s = lane, seg = w;
        float acc = 0.f;
#pragma unroll
        for (int i = 0; i < 32; i++) {
            float v = tile[s][seg * 32 + i];
            acc += v * v;
        }
        psum[seg][s] = acc;
        __syncthreads();
        if (t < 32) {
            float tot = 0.f;
#pragma unroll
            for (int g = 0; g < 8; g++) tot += psum[g][t];
            invs[t] = 1.0f / fmaxf(sqrtf(tot), 1e-12f);
        }
        __syncthreads();
    }

    // write transposed: warp w handles s = p*8+w, lanes = c (coalesced)
#pragma unroll
    for (int p = 0; p < 4; p++) {
        int s = p * 8 + w;
        float inv = (z != 0) ? invs[s] : 1.0f;
        size_t o = ((size_t)b * NS + s0 + s) * NC;
        if (z >= 2) {
            float* out = (z == 2) ? g_qgt : g_kgt;
#pragma unroll
            for (int q = 0; q < 8; q++) {
                int c = q * 32 + lane;
                out[o + c] = tile[s][c] * inv;
            }
        } else if (z == 0) {
#pragma unroll
            for (int q = 0; q < 8; q++) {
                int c = q * 32 + lane;
                g_qbt_hi[o + c] = __float2bfloat16_rn(tile[s][c]);
            }
        } else {
#pragma unroll
            for (int q = 0; q < 8; q++) {
                int c = q * 32 + lane;
                float v = tile[s][c] * inv;
                __nv_bfloat16 hi = __float2bfloat16_rn(v);
                __nv_bfloat16 lo = __float2bfloat16_rn(v - __bfloat162float(hi));
                g_kbt_hi[o + c] = hi; g_kbt_lo[o + c] = lo;
            }
        }
    }
    if (z == 0 && t < 32) g_arg[b * NS + s0 + t] = 0ull;   // graph replay reset
    if (z == 0 && b == 0 && blockIdx.x == 0 && t == 0) g_loss = 0.f;
}

// ---------------- Kernel C: GEMM + argmax (warp-specialized tcgen05) ------
__device__ __forceinline__ unsigned long long pack_key(float v, int j) {
    unsigned int u = __float_as_uint(v);
    u = (u & 0x80000000u) ? ~u : (u | 0x80000000u);     // order-preserving
    return ((unsigned long long)u << 32) | (unsigned int)(0xFFFFFFFFu - (unsigned int)j);
}

// SMEM (dynamic, 1024-aligned): B stage k (k=0..2) @ k*65536 (hi 32K, lo 32K)
#define SM_BBUF(k)   ((k) * 65536)
#define SM_BLO_OFF   32768
#define SM_PTR       196608
#define SM_FULL(s)   (196624 + (s) * 8)
#define SM_EMPTY(s)  (196648 + (s) * 8)
#define SM_CM(k)     (196672 + (k) * 8)
#define SMEM_SZ      (196608 + 2048)

__global__ __launch_bounds__(256, 1)
void mma_argmax_kernel() {
    extern __shared__ char dsm_raw[];
    uint32_t sm0 = smem_u32(dsm_raw);
    uint32_t smb = (sm0 + 1023) & ~1023u;       // 1024-aligned base
    char* base = dsm_raw + (smb - sm0);

    int tid = threadIdx.x;                       // 256 threads
    int wid = tid >> 5, lane = tid & 31;
    int jh = blockIdx.x;                         // j half: 0/1
    int i0 = blockIdx.y * 128;
    int b  = blockIdx.z;

#if HAS_TCGEN05
    if (wid == 0) TCGEN05_ALLOC(smb + SM_PTR, 512);
    if (tid == 0) {
#pragma unroll
        for (int s = 0; s < 3; s++) {
            MBARRIER_INIT(smb + SM_FULL(s), 128);   // all loader threads
            MBARRIER_INIT(smb + SM_EMPTY(s), 1);    // warp0 lane0
        }
        MBARRIER_INIT(smb + SM_CM(0), 1);
        MBARRIER_INIT(smb + SM_CM(1), 1);
    }
    __syncthreads();                              // only block-wide sync

    if (tid >= 128) {
        // ================= loader warps (4-7) =================
        int t2 = tid - 128;
        for (int c = 0; c < 8; c++) {
            int s = c % 3, u = c / 3;
            MBARRIER_WAIT_PARITY(smb + SM_EMPTY(s), (u & 1) ^ 1);
            int jb = jh * 512 + c * 64;
            const char* sh = (const char*)(g_kbt_hi + ((size_t)b * NS + jb) * NC);
            const char* sl = (const char*)(g_kbt_lo + ((size_t)b * NS + jb) * NC);
            char* dh = base + SM_BBUF(s);
            char* dl = dh + SM_BLO_OFF;
#pragma unroll
            for (int it = 0; it < 16; it++) {     // 2048 16B-chunks / 128 thr
                int idx = t2 + it * 128;
                int row = idx >> 5;
                int cb  = (idx & 31) * 16;
                uint32_t off = (uint32_t)(((row >> 3) + (cb >> 7) * 8) * 1024
                                          + (row & 7) * 128 + (cb & 127));
                uint32_t sw = SW128(off);
                *(uint4*)(dh + sw) = *(const uint4*)(sh + (size_t)row * 512 + cb);
                *(uint4*)(dl + sw) = *(const uint4*)(sl + (size_t)row * 512 + cb);
            }
            FENCE_ASYNC();
            MBARRIER_ARRIVE(smb + SM_FULL(s));
        }
        return;   // loaders exit
    }

    // ================= compute warps (0-3) =================
    uint32_t tmem;
    asm volatile("ld.shared.b32 %0, [%1];" : "=r"(tmem) : "r"(smb + SM_PTR));
    uint32_t tA_hi = tmem;            // A hi: cols 0..127
    uint32_t tD0   = tmem + 128;      // D ping: cols 128..191
    uint32_t tD1   = tmem + 192;      // D pong: cols 192..255

    // ---- A (q tile, 128 rows x 256 bf16 hi) -> TMEM ----
    {
        uint32_t wo = (uint32_t)(wid) << 21;
        size_t rowoff = ((size_t)b * NS + i0 + tid) * NC;
        const uint4* srcs = (const uint4*)(g_qbt_hi + rowoff);
#pragma unroll
        for (int qtr = 0; qtr < 4; qtr++) {       // 4 x 32-reg stores
            uint32_t r[32];
#pragma unroll
            for (int q = 0; q < 8; q++) {
                uint4 v = srcs[qtr * 8 + q];
                r[q * 4 + 0] = v.x; r[q * 4 + 1] = v.y;
                r[q * 4 + 2] = v.z; r[q * 4 + 3] = v.w;
            }
            TCGEN05_ST_X32(tA_hi + qtr * 32 + wo, r);
        }
        TCGEN05_WAIT_ST();
    }
    TCGEN05_FENCE_BEFORE();
    NAMED_BAR(1, 128);                            // A fully in TMEM

    // issue one chunk's 32 MMAs (AhBh + AhBl); commit on cm[chunk&1]
    auto issue_chunk = [&](int chunk) {
        int s = chunk % 3;
        uint32_t tD = (chunk & 1) ? tD1 : tD0;
        uint64_t bh = MAKE_SMEM_DESC(smb + SM_BBUF(s));
        uint64_t bl = MAKE_SMEM_DESC(smb + SM_BBUF(s) + SM_BLO_OFF);
#pragma unroll
        for (int ks = 0; ks < 16; ks++) {
            uint32_t aoff = ks * 8;
            uint64_t boff = (uint64_t)((ks >> 2) * 512 + (ks & 3) * 2);
            mma_f16_ts(tD, tA_hi + aoff, bh + boff, MMA_IDESC, ks != 0);
            mma_f16_ts(tD, tA_hi + aoff, bl + boff, MMA_IDESC, 1u);
        }
        TCGEN05_COMMIT(smb + SM_CM(chunk & 1));
    };

    // prologue: issue chunk 0 as soon as loaders deliver stage 0
    if (wid == 0) {
        MBARRIER_WAIT_PARITY(smb + SM_FULL(0), 0);
        TCGEN05_FENCE_AFTER();
        if (elect_one_pred()) issue_chunk(0);
    }

    float best = -3.4e38f;
    int   bj   = 0;
    int   jrow_base = jh * 512;

    for (int c = 0; c < 8; c++) {
        // issue chunk c+1 (B full-wait; D(c+1) drained at iter c-1's bar)
        if (c < 7 && wid == 0) {
            int n = c + 1;
            MBARRIER_WAIT_PARITY(smb + SM_FULL(n % 3), (n / 3) & 1);
            TCGEN05_FENCE_AFTER();
            if (elect_one_pred()) issue_chunk(n);
        }
        // wait chunk c complete
        MBARRIER_WAIT_PARITY(smb + SM_CM(c & 1), (c >> 1) & 1);
        TCGEN05_FENCE_AFTER();
        if (wid == 0 && lane == 0) MBARRIER_ARRIVE(smb + SM_EMPTY(c % 3));

        // readout + argmax: 4 groups of 16 cols
        uint32_t tD = (c & 1) ? tD1 : tD0;
#pragma unroll
        for (int g = 0; g < 4; g++) {
            uint32_t r[16];
            TCGEN05_LD_X16(r, tD + g * 16);
            TCGEN05_WAIT_LD();
            float v[16], w[16];
#pragma unroll
            for (int i = 0; i < 16; i++) { v[i] = __uint_as_float(r[i]); w[i] = v[i]; }
#pragma unroll
            for (int off = 8; off; off >>= 1)
#pragma unroll
                for (int i = 0; i < off; i++) w[i] = fmaxf(w[i], w[i + off]);
            float m = w[0];
            int gi = 15;
#pragma unroll
            for (int i = 15; i >= 0; i--) if (v[i] == m) gi = i;   // smallest i
            if (m > best) { best = m; bj = jrow_base + c * 64 + g * 16 + gi; }
        }
        TCGEN05_FENCE_BEFORE();
        NAMED_BAR(1, 128);      // D(c) drained before MMA(c+2) issue
    }

    int row = i0 + wid * 32 + lane;
    atomicMax(&g_arg[b * NS + row], pack_key(best, bj));

    NAMED_BAR(1, 128);
    if (wid == 0) { TCGEN05_RELINQ(); TCGEN05_DEALLOC(tmem, 512); }
#else
    // ---------- fallback (non-a target): smem-cached dot products ----------
    float* As = (float*)base;                    // 128*257*4 = 131584 B
    float* kv = As + 128 * 257;                  // 256 floats
    __syncthreads();
    if (tid < 128) {
        size_t rowoff = ((size_t)b * NS + i0 + tid) * NC;
        const __nv_bfloat16* h = g_qbt_hi + rowoff;
#pragma unroll 8
        for (int c = 0; c < NC; c++)
            As[tid * 257 + c] = __bfloat162float(h[c]);
    }
    __syncthreads();

    float best = -3.4e38f;
    int   bj   = 0;
    for (int j = 0; j < 512; j++) {
        int jr = jh * 512 + j;
        size_t ko = ((size_t)b * NS + jr) * NC;
        __syncthreads();                          // protect kv from prev iter
        kv[tid] = __bfloat162float(g_kbt_hi[ko + tid])
                + __bfloat162float(g_kbt_lo[ko + tid]);
        __syncthreads();
        if (tid < 128) {
            float dot = 0.f;
#pragma unroll 8
            for (int c = 0; c < NC; c++) dot += As[tid * 257 + c] * kv[c];
            if (dot > best) { best = dot; bj = jr; }  // ascending j
        }
    }
    if (tid < 128)
        atomicMax(&g_arg[b * NS + i0 + tid], pack_key(best, bj));
    (void)wid; (void)lane;
#endif
}

// ---------------- Kernel D: jax PARTITIONABLE threefry -> uniform -> neg_idx -
__device__ __forceinline__ void threefry2x32(uint32_t k0, uint32_t k1,
                                             uint32_t x0, uint32_t x1,
                                             uint32_t& o0, uint32_t& o1) {
    uint32_t ks0 = k0, ks1 = k1, ks2 = k0 ^ k1 ^ 0x1BD11BDAu;
    const int r0[4] = {13, 15, 26, 6};
    const int r1[4] = {17, 29, 16, 24};
    x0 += ks0; x1 += ks1;
    uint32_t ks[3] = {ks0, ks1, ks2};
#pragma unroll
    for (int i = 0; i < 5; i++) {
        const int* rr = (i & 1) ? r1 : r0;
#pragma unroll
        for (int j = 0; j < 4; j++) {
            x0 += x1;
            x1 = (x1 << rr[j]) | (x1 >> (32 - rr[j]));
            x1 ^= x0;
        }
        x0 += ks[(i + 1) % 3];
        x1 += ks[(i + 2) % 3] + (uint32_t)(i + 1);
    }
    o0 = x0; o1 = x1;
}

__global__ void negidx_kernel(const int* __restrict__ labels_raw) {
    __shared__ float uf[1024];
    __shared__ int lab[32];
    __shared__ int is64;
    int t = threadIdx.x;   // 1024 threads, one per element of u (32x32)
    uint32_t o0, o1;
    threefry2x32(0u, 42u, 0u, (uint32_t)t, o0, o1);   // counter = (hi=0, lo=n)
    uint32_t bits = o0 ^ o1;                           // partitionable fold
    uf[t] = __uint_as_float((bits >> 9) | 0x3f800000u) - 1.0f;
    if (t == 0) {
        int all0 = 1;
        for (int i = 1; i < 32; i += 2) all0 &= (labels_raw[i] == 0);
        is64 = all0;
    }
    __syncthreads();
    if (t < 32) lab[t] = is64 ? labels_raw[2 * t] : labels_raw[t];
    __syncthreads();
    if (t < 32) {
        int lb = lab[t];
        float best = -2.0f; int bi = 0;
        for (int j = 0; j < 32; j++) {
            float v = (lab[j] != lb) ? uf[t * 32 + j] : -1.0f;
            if (v > best) { best = v; bi = j; }    // first-max ties
        }
        g_negidx[t] = bi;
    }
}

// ---------------- Kernel E: loss terms (warp per (b,i)) ----------------
__global__ void loss_kernel() {
    __shared__ float part[8];
    int wid = threadIdx.x >> 5, lane = threadIdx.x & 31;
    int gw = blockIdx.x * 8 + wid;          // 0..32767
    int b = gw >> 10, i = gw & 1023;
    unsigned long long key = g_arg[gw];
    int idx = (int)(0xFFFFFFFFu - (unsigned int)(key & 0xFFFFFFFFull));
    int nb = g_negidx[b];
    const float4* q  = (const float4*)(g_qgt + (size_t)gw * NC);
    const float4* kp = (const float4*)(g_kgt + ((size_t)b  * NS + idx) * NC);
    const float4* kn = (const float4*)(g_kgt + ((size_t)nb * NS + i)   * NC);
    float dp = 0.f, dn = 0.f;
#pragma unroll
    for (int u = 0; u < 2; u++) {
        int c4 = lane + u * 32;
        float4 qv = q[c4], pv = kp[c4], nv = kn[c4];
        dp += qv.x * pv.x + qv.y * pv.y + qv.z * pv.z + qv.w * pv.w;
        dn += qv.x * nv.x + qv.y * nv.y + qv.z * nv.z + qv.w * nv.w;
    }
#pragma unroll
    for (int off = 16; off; off >>= 1) {
        dp += __shfl_xor_sync(0xFFFFFFFFu, dp, off);
        dn += __shfl_xor_sync(0xFFFFFFFFu, dn, off);
    }
    if (lane == 0) {
        float p = dp * 10.0f;   // / TEMP
        float n = dn * 10.0f;
        part[wid] = logf(expf(p) + expf(n) + 1e-6f) - p;
    }
    __syncthreads();
    if (threadIdx.x == 0) {
        float s = 0.f;
        for (int w = 0; w < 8; w++) s += part[w];
        atomicAdd(&g_loss, s);
    }
}

__global__ void finalize_kernel(float* out) {
    out[0] = g_loss * (1.0f / 32768.0f);   // mean * LAM(=1)
}

// ---------------- entry ----------------
extern "C" void kernel_launch(void* const* d_in, const int* in_sizes, int n_in,
                              void* d_out, int out_size) {
    const float* q_b    = (const float*)d_in[0];
    const float* k_b    = (const float*)d_in[1];
    const float* q_grid = (const float*)d_in[2];
    const float* k_grid = (const float*)d_in[3];
    const int*   labels = (const int*)d_in[4];

    static int smem_set = 0;
    if (!smem_set) {
        cudaFuncSetAttribute(mma_argmax_kernel,
                             cudaFuncAttributeMaxDynamicSharedMemorySize, SMEM_SZ);
        smem_set = 1;
    }

    prep_kernel<<<dim3(32, 32, 4), 256>>>(q_b, k_b, q_grid, k_grid);
    negidx_kernel<<<1, 1024>>>(labels);
    mma_argmax_kernel<<<dim3(2, 8, 32), 256, SMEM_SZ>>>();
    loss_kernel<<<4096, 256>>>();
    finalize_kernel<<<1, 1>>>((float*)d_out);
}

// round 17
// speedup vs baseline: 1.9509x; 1.0549x over previous
#include <cuda_runtime.h>
#include <cuda_bf16.h>
#include <cstdint>
#include <math.h>

#define NB   32
#define NC   256
#define NS   1024
#define NBS  (NB * NS)     // 32768
#define NCS  (NC * NS)     // 262144

// tcgen05 exists only on arch-specific (a) targets; the harness also compiles
// a compute_103 (non-a) pass, which must still build AND be correct.
#if defined(__CUDA_ARCH__) && (defined(__CUDA_ARCH_FEAT_SM103_ALL) || defined(__CUDA_ARCH_FEAT_SM100_ALL) || defined(__CUDA_ARCH_FEAT_SM101_ALL))
#define HAS_TCGEN05 1
#else
#define HAS_TCGEN05 0
#endif

// ---------------- device scratch (no allocations allowed) ----------------
__device__ __nv_bfloat16 g_qgt[(size_t)NB * NS * NC];  // normalized q_grid, bf16
__device__ __nv_bfloat16 g_kgt[(size_t)NB * NS * NC];  // normalized k_grid, bf16
__device__ __nv_bfloat16 g_qbt[(size_t)NB * NS * NC];  // raw q_b, [B,S,C] bf16
__device__ __nv_bfloat16 g_kbt_hi[(size_t)NB * NS * NC];  // k_b*1/||k|| hi
__device__ __nv_bfloat16 g_kbt_lo[(size_t)NB * NS * NC];  // k_b*1/||k|| lo
__device__ unsigned long long g_arg[NBS];      // packed (value, ~j) argmax
__device__ int   g_negidx[NB];
__device__ float g_loss;

// ---------------- PTX helpers ----------------
__device__ __forceinline__ uint32_t smem_u32(const void* p) {
    uint32_t a;
    asm("{ .reg .u64 t; cvta.to.shared.u64 t, %1; cvt.u32.u64 %0, t; }"
        : "=r"(a) : "l"(p));
    return a;
}

#if HAS_TCGEN05
__device__ __forceinline__ uint32_t elect_one_pred() {
    uint32_t pred;
    asm volatile("{\n\t.reg .pred p;\n\telect.sync _|p, 0xFFFFFFFF;\n\t"
                 "selp.b32 %0, 1, 0, p;\n\t}" : "=r"(pred));
    return pred;
}
#define TCGEN05_ALLOC(smem_addr, nCols) \
    asm volatile("tcgen05.alloc.cta_group::1.sync.aligned.shared::cta.b32 [%0], %1;" \
        :: "r"((uint32_t)(smem_addr)), "r"((uint32_t)(nCols)) : "memory")
#define TCGEN05_DEALLOC(tmem, nCols) \
    asm volatile("tcgen05.dealloc.cta_group::1.sync.aligned.b32 %0, %1;" \
        :: "r"(tmem), "r"((uint32_t)(nCols)))
#define TCGEN05_RELINQ() \
    asm volatile("tcgen05.relinquish_alloc_permit.cta_group::1.sync.aligned;")
#define TCGEN05_WAIT_LD() asm volatile("tcgen05.wait::ld.sync.aligned;" ::: "memory")
#define TCGEN05_WAIT_ST() asm volatile("tcgen05.wait::st.sync.aligned;" ::: "memory")
#define TCGEN05_FENCE_BEFORE() asm volatile("tcgen05.fence::before_thread_sync;" ::: "memory")
#define TCGEN05_FENCE_AFTER()  asm volatile("tcgen05.fence::after_thread_sync;" ::: "memory")
#define TCGEN05_COMMIT(mbar) \
    asm volatile("tcgen05.commit.cta_group::1.mbarrier::arrive::one.shared::cluster.b64 [%0];" \
        :: "r"((uint32_t)(mbar)) : "memory")
#define FENCE_ASYNC() asm volatile("fence.proxy.async.shared::cta;" ::: "memory")
#define MBARRIER_INIT(mbar, cnt) \
    asm volatile("mbarrier.init.shared.b64 [%0], %1;" \
        :: "r"((uint32_t)(mbar)), "r"((uint32_t)(cnt)) : "memory")
#define MBARRIER_ARRIVE(mbar) \
    asm volatile("mbarrier.arrive.shared.b64 _, [%0];" \
        :: "r"((uint32_t)(mbar)) : "memory")
#define MBARRIER_WAIT_PARITY(mbar, par) do { \
    uint32_t _m = (uint32_t)(mbar); uint32_t _p = (uint32_t)(par); uint32_t _d; \
    asm volatile("{\n\t.reg .pred p;\n\t" \
        "mbarrier.try_wait.parity.acquire.cta.shared::cta.b64 p, [%1], %2;\n\t" \
        "selp.b32 %0, 1, 0, p;\n\t}" : "=r"(_d) : "r"(_m), "r"(_p) : "memory"); \
    if (!_d) { \
        asm volatile("{\n\t.reg .pred P1;\n\t" \
            "WL_%=:\n\t" \
            "mbarrier.try_wait.parity.acquire.cta.shared::cta.b64 P1, [%0], %1, 0x989680;\n\t" \
            "@P1 bra.uni WD_%=;\n\tbra.uni WL_%=;\n\tWD_%=:\n\t}" \
            :: "r"(_m), "r"(_p) : "memory"); \
    } } while(0)
#define NAMED_BAR(id, n) \
    asm volatile("bar.sync %0, %1;" :: "r"(id), "r"(n) : "memory")

// TS-mode bf16 MMA: D(TMEM) += A(TMEM) * B(SMEM desc)^T
__device__ __forceinline__ void mma_f16_ts(uint32_t d_tmem, uint32_t a_tmem,
                                           uint64_t b_desc, uint32_t idesc,
                                           uint32_t enable) {
    asm volatile("{\n\t.reg .pred p;\n\tsetp.ne.u32 p, %4, 0;\n\t"
        "tcgen05.mma.cta_group::1.kind::f16 [%0], [%1], %2, %3, {%5,%5,%5,%5}, p;\n\t}"
        :: "r"(d_tmem), "r"(a_tmem), "l"(b_desc), "r"(idesc), "r"(enable), "r"(0u)
        : "memory");
}
#define TCGEN05_ST_X32(tmem, r) \
    asm volatile("tcgen05.st.sync.aligned.32x32b.x32.b32 [%0], " \
        "{%1,%2,%3,%4,%5,%6,%7,%8,%9,%10,%11,%12,%13,%14,%15,%16," \
        "%17,%18,%19,%20,%21,%22,%23,%24,%25,%26,%27,%28,%29,%30,%31,%32};" \
        :: "r"(tmem), \
        "r"((r)[0]),"r"((r)[1]),"r"((r)[2]),"r"((r)[3]),"r"((r)[4]),"r"((r)[5]),"r"((r)[6]),"r"((r)[7]), \
        "r"((r)[8]),"r"((r)[9]),"r"((r)[10]),"r"((r)[11]),"r"((r)[12]),"r"((r)[13]),"r"((r)[14]),"r"((r)[15]), \
        "r"((r)[16]),"r"((r)[17]),"r"((r)[18]),"r"((r)[19]),"r"((r)[20]),"r"((r)[21]),"r"((r)[22]),"r"((r)[23]), \
        "r"((r)[24]),"r"((r)[25]),"r"((r)[26]),"r"((r)[27]),"r"((r)[28]),"r"((r)[29]),"r"((r)[30]),"r"((r)[31]) \
        : "memory")
#define TCGEN05_LD_X16(r, tmem) \
    asm volatile("tcgen05.ld.sync.aligned.32x32b.x16.b32 " \
        "{%0,%1,%2,%3,%4,%5,%6,%7,%8,%9,%10,%11,%12,%13,%14,%15}, [%16];" \
        : "=r"((r)[0]),"=r"((r)[1]),"=r"((r)[2]),"=r"((r)[3]), \
          "=r"((r)[4]),"=r"((r)[5]),"=r"((r)[6]),"=r"((r)[7]), \
          "=r"((r)[8]),"=r"((r)[9]),"=r"((r)[10]),"=r"((r)[11]), \
          "=r"((r)[12]),"=r"((r)[13]),"=r"((r)[14]),"=r"((r)[15]) \
        : "r"(tmem))

static constexpr uint64_t SMEM_DESC_BASE_SW128 =
    (uint64_t(2) << 61) | (uint64_t(1) << 46) | (uint64_t(64) << 32) | (uint64_t(1) << 16);
#define MAKE_SMEM_DESC(a) (SMEM_DESC_BASE_SW128 | ((uint64_t)((a) >> 4) & 0x3FFF))
#define SW128(off) ((off) ^ (((off) >> 3) & 0x70))
// idesc: f32 accum, bf16 a/b, N=64, M=128
#define MMA_IDESC 0x8100490u
#endif  // HAS_TCGEN05

// ---------------- Kernel A: fused norms + normalize + transpose ----------
// grid (32 s-tiles, 32 b, 4 tensors), block 256.
// z=0: q_b raw -> g_qbt bf16 (+ g_arg/g_loss reset)
// z=1: k_b * 1/||col|| -> g_kbt hi/lo (argmax-competing operand keeps hi/lo)
// z=2: q_grid * 1/||col|| -> g_qgt bf16
// z=3: k_grid * 1/||col|| -> g_kgt bf16
__global__ __launch_bounds__(256, 2)
void prep_kernel(const float* __restrict__ qb, const float* __restrict__ kb,
                 const float* __restrict__ qg, const float* __restrict__ kg) {
    __shared__ float tile[32][257];
    __shared__ float psum[8][32];
    __shared__ float invs[32];
    int z  = blockIdx.z;
    int b  = blockIdx.y;
    int s0 = blockIdx.x * 32;
    const float* in = (z == 0) ? qb : (z == 1) ? kb : (z == 2) ? qg : kg;
    int t = threadIdx.x;
    int w = t >> 5, lane = t & 31;

    // load [c][s] -> tile[s][c]; coalesced over s, conflict-free stores
    const float* src = in + (size_t)b * NCS + s0 + lane;
#pragma unroll
    for (int p = 0; p < 32; p++) {
        int c = p * 8 + w;
        tile[lane][c] = src[(size_t)c * NS];
    }
    __syncthreads();

    if (z != 0) {
        int s = lane, seg = w;
        float acc = 0.f;
#pragma unroll
        for (int i = 0; i < 32; i++) {
            float v = tile[s][seg * 32 + i];
            acc += v * v;
        }
        psum[seg][s] = acc;
        __syncthreads();
        if (t < 32) {
            float tot = 0.f;
#pragma unroll
            for (int g = 0; g < 8; g++) tot += psum[g][t];
            invs[t] = 1.0f / fmaxf(sqrtf(tot), 1e-12f);
        }
        __syncthreads();
    }

    // write transposed: warp w handles s = p*8+w, lanes = c (coalesced)
#pragma unroll
    for (int p = 0; p < 4; p++) {
        int s = p * 8 + w;
        float inv = (z != 0) ? invs[s] : 1.0f;
        size_t o = ((size_t)b * NS + s0 + s) * NC;
        if (z == 1) {
#pragma unroll
            for (int q = 0; q < 8; q++) {
                int c = q * 32 + lane;
                float v = tile[s][c] * inv;
                __nv_bfloat16 hi = __float2bfloat16_rn(v);
                __nv_bfloat16 lo = __float2bfloat16_rn(v - __bfloat162float(hi));
                g_kbt_hi[o + c] = hi; g_kbt_lo[o + c] = lo;
            }
        } else {
            __nv_bfloat16* out = (z == 0) ? g_qbt : (z == 2) ? g_qgt : g_kgt;
#pragma unroll
            for (int q = 0; q < 8; q++) {
                int c = q * 32 + lane;
                out[o + c] = __float2bfloat16_rn(tile[s][c] * inv);
            }
        }
    }
    if (z == 0 && t < 32) g_arg[b * NS + s0 + t] = 0ull;   // graph replay reset
    if (z == 0 && b == 0 && blockIdx.x == 0 && t == 0) g_loss = 0.f;
}

// ---------------- Kernel C: GEMM + argmax (warp-specialized tcgen05) ------
__device__ __forceinline__ unsigned long long pack_key(float v, int j) {
    unsigned int u = __float_as_uint(v);
    u = (u & 0x80000000u) ? ~u : (u | 0x80000000u);     // order-preserving
    return ((unsigned long long)u << 32) | (unsigned int)(0xFFFFFFFFu - (unsigned int)j);
}

// SMEM (dynamic, 1024-aligned): B stage k (k=0..2) @ k*65536 (hi 32K, lo 32K)
#define SM_BBUF(k)   ((k) * 65536)
#define SM_BLO_OFF   32768
#define SM_PTR       196608
#define SM_FULL(s)   (196624 + (s) * 8)
#define SM_EMPTY(s)  (196648 + (s) * 8)
#define SM_CM(k)     (196672 + (k) * 8)
#define SMEM_SZ      (196608 + 2048)

__global__ __launch_bounds__(256, 1)
void mma_argmax_kernel() {
    extern __shared__ char dsm_raw[];
    uint32_t sm0 = smem_u32(dsm_raw);
    uint32_t smb = (sm0 + 1023) & ~1023u;       // 1024-aligned base
    char* base = dsm_raw + (smb - sm0);

    int tid = threadIdx.x;                       // 256 threads
    int wid = tid >> 5, lane = tid & 31;
    int jh = blockIdx.x;                         // j half: 0/1
    int i0 = blockIdx.y * 128;
    int b  = blockIdx.z;

#if HAS_TCGEN05
    if (wid == 0) TCGEN05_ALLOC(smb + SM_PTR, 256);
    if (tid == 0) {
#pragma unroll
        for (int s = 0; s < 3; s++) {
            MBARRIER_INIT(smb + SM_FULL(s), 128);   // all loader threads
            MBARRIER_INIT(smb + SM_EMPTY(s), 1);    // warp0 lane0
        }
        MBARRIER_INIT(smb + SM_CM(0), 1);
        MBARRIER_INIT(smb + SM_CM(1), 1);
    }
    __syncthreads();                              // only block-wide sync

    if (tid >= 128) {
        // ================= loader warps (4-7) =================
        int t2 = tid - 128;
        for (int c = 0; c < 8; c++) {
            int s = c % 3, u = c / 3;
            MBARRIER_WAIT_PARITY(smb + SM_EMPTY(s), (u & 1) ^ 1);
            int jb = jh * 512 + c * 64;
            const char* sh = (const char*)(g_kbt_hi + ((size_t)b * NS + jb) * NC);
            const char* sl = (const char*)(g_kbt_lo + ((size_t)b * NS + jb) * NC);
            char* dh = base + SM_BBUF(s);
            char* dl = dh + SM_BLO_OFF;
#pragma unroll
            for (int it = 0; it < 16; it++) {     // 2048 16B-chunks PER TENSOR
                int idx = t2 + it * 128;
                int row = idx >> 5;
                int cb  = (idx & 31) * 16;
                uint32_t off = (uint32_t)(((row >> 3) + (cb >> 7) * 8) * 1024
                                          + (row & 7) * 128 + (cb & 127));
                uint32_t sw = SW128(off);
                *(uint4*)(dh + sw) = *(const uint4*)(sh + (size_t)row * 512 + cb);
                *(uint4*)(dl + sw) = *(const uint4*)(sl + (size_t)row * 512 + cb);
            }
            FENCE_ASYNC();
            MBARRIER_ARRIVE(smb + SM_FULL(s));
        }
        return;   // loaders exit
    }

    // ================= compute warps (0-3) =================
    uint32_t tmem;
    asm volatile("ld.shared.b32 %0, [%1];" : "=r"(tmem) : "r"(smb + SM_PTR));
    uint32_t tA  = tmem;              // A: cols 0..127
    uint32_t tD0 = tmem + 128;        // D ping: cols 128..191
    uint32_t tD1 = tmem + 192;        // D pong: cols 192..255

    // ---- A (q tile, 128 rows x 256 bf16) -> TMEM ----
    {
        uint32_t wo = (uint32_t)(wid) << 21;
        size_t rowoff = ((size_t)b * NS + i0 + tid) * NC;
        const uint4* srcs = (const uint4*)(g_qbt + rowoff);
#pragma unroll
        for (int qtr = 0; qtr < 4; qtr++) {       // 4 x 32-reg stores
            uint32_t r[32];
#pragma unroll
            for (int q = 0; q < 8; q++) {
                uint4 v = srcs[qtr * 8 + q];
                r[q * 4 + 0] = v.x; r[q * 4 + 1] = v.y;
                r[q * 4 + 2] = v.z; r[q * 4 + 3] = v.w;
            }
            TCGEN05_ST_X32(tA + qtr * 32 + wo, r);
        }
        TCGEN05_WAIT_ST();
    }
    TCGEN05_FENCE_BEFORE();
    NAMED_BAR(1, 128);                            // A fully in TMEM

    // issue one chunk's 32 MMAs (AhBh + AhBl); commit on cm[chunk&1]
    auto issue_chunk = [&](int chunk) {
        int s = chunk % 3;
        uint32_t tD = (chunk & 1) ? tD1 : tD0;
        uint64_t bh = MAKE_SMEM_DESC(smb + SM_BBUF(s));
        uint64_t bl = MAKE_SMEM_DESC(smb + SM_BBUF(s) + SM_BLO_OFF);
#pragma unroll
        for (int ks = 0; ks < 16; ks++) {
            uint32_t aoff = ks * 8;
            uint64_t boff = (uint64_t)((ks >> 2) * 512 + (ks & 3) * 2);
            mma_f16_ts(tD, tA + aoff, bh + boff, MMA_IDESC, ks != 0);
            mma_f16_ts(tD, tA + aoff, bl + boff, MMA_IDESC, 1u);
        }
        TCGEN05_COMMIT(smb + SM_CM(chunk & 1));
    };

    // prologue: issue chunk 0 as soon as loaders deliver stage 0
    if (wid == 0) {
        MBARRIER_WAIT_PARITY(smb + SM_FULL(0), 0);
        TCGEN05_FENCE_AFTER();
        if (elect_one_pred()) issue_chunk(0);
    }

    float best = -3.4e38f;
    int   bj   = 0;
    int   jrow_base = jh * 512;

    for (int c = 0; c < 8; c++) {
        // issue chunk c+1 (B full-wait; D(c+1) drained at iter c-1's bar)
        if (c < 7 && wid == 0) {
            int n = c + 1;
            MBARRIER_WAIT_PARITY(smb + SM_FULL(n % 3), (n / 3) & 1);
            TCGEN05_FENCE_AFTER();
            if (elect_one_pred()) issue_chunk(n);
        }
        // wait chunk c complete
        MBARRIER_WAIT_PARITY(smb + SM_CM(c & 1), (c >> 1) & 1);
        TCGEN05_FENCE_AFTER();
        if (wid == 0 && lane == 0) MBARRIER_ARRIVE(smb + SM_EMPTY(c % 3));

        // readout + argmax: 4 groups of 16 cols
        uint32_t tD = (c & 1) ? tD1 : tD0;
#pragma unroll
        for (int g = 0; g < 4; g++) {
            uint32_t r[16];
            TCGEN05_LD_X16(r, tD + g * 16);
            TCGEN05_WAIT_LD();
            float v[16], w[16];
#pragma unroll
            for (int i = 0; i < 16; i++) { v[i] = __uint_as_float(r[i]); w[i] = v[i]; }
#pragma unroll
            for (int off = 8; off; off >>= 1)
#pragma unroll
                for (int i = 0; i < off; i++) w[i] = fmaxf(w[i], w[i + off]);
            float m = w[0];
            int gi = 15;
#pragma unroll
            for (int i = 15; i >= 0; i--) if (v[i] == m) gi = i;   // smallest i
            if (m > best) { best = m; bj = jrow_base + c * 64 + g * 16 + gi; }
        }
        TCGEN05_FENCE_BEFORE();
        NAMED_BAR(1, 128);      // D(c) drained before MMA(c+2) issue
    }

    int row = i0 + wid * 32 + lane;
    atomicMax(&g_arg[b * NS + row], pack_key(best, bj));

    NAMED_BAR(1, 128);
    if (wid == 0) { TCGEN05_RELINQ(); TCGEN05_DEALLOC(tmem, 256); }
#else
    // ---------- fallback (non-a target): smem-cached dot products ----------
    // As: 128 rows x 264 bf16 (padded) = 67584 B; kv: 256 floats
    __nv_bfloat16* As = (__nv_bfloat16*)base;
    float* kv = (float*)(base + 128 * 264 * 2);
    __syncthreads();
    if (tid < 128) {
        size_t rowoff = ((size_t)b * NS + i0 + tid) * NC;
        const __nv_bfloat16* h = g_qbt + rowoff;
#pragma unroll 8
        for (int c = 0; c < NC; c++)
            As[tid * 264 + c] = h[c];
    }
    __syncthreads();

    float best = -3.4e38f;
    int   bj   = 0;
    for (int j = 0; j < 512; j++) {
        int jr = jh * 512 + j;
        size_t ko = ((size_t)b * NS + jr) * NC;
        __syncthreads();                          // protect kv from prev iter
        kv[tid] = __bfloat162float(g_kbt_hi[ko + tid])
                + __bfloat162float(g_kbt_lo[ko + tid]);
        __syncthreads();
        if (tid < 128) {
            float dot = 0.f;
#pragma unroll 8
            for (int c = 0; c < NC; c++)
                dot += __bfloat162float(As[tid * 264 + c]) * kv[c];
            if (dot > best) { best = dot; bj = jr; }  // ascending j
        }
    }
    if (tid < 128)
        atomicMax(&g_arg[b * NS + i0 + tid], pack_key(best, bj));
    (void)wid; (void)lane;
#endif
}

// ---------------- Kernel D: jax PARTITIONABLE threefry -> uniform -> neg_idx -
__device__ __forceinline__ void threefry2x32(uint32_t k0, uint32_t k1,
                                             uint32_t x0, uint32_t x1,
                                             uint32_t& o0, uint32_t& o1) {
    uint32_t ks0 = k0, ks1 = k1, ks2 = k0 ^ k1 ^ 0x1BD11BDAu;
    const int r0[4] = {13, 15, 26, 6};
    const int r1[4] = {17, 29, 16, 24};
    x0 += ks0; x1 += ks1;
    uint32_t ks[3] = {ks0, ks1, ks2};
#pragma unroll
    for (int i = 0; i < 5; i++) {
        const int* rr = (i & 1) ? r1 : r0;
#pragma unroll
        for (int j = 0; j < 4; j++) {
            x0 += x1;
            x1 = (x1 << rr[j]) | (x1 >> (32 - rr[j]));
            x1 ^= x0;
        }
        x0 += ks[(i + 1) % 3];
        x1 += ks[(i + 2) % 3] + (uint32_t)(i + 1);
    }
    o0 = x0; o1 = x1;
}

__global__ void negidx_kernel(const int* __restrict__ labels_raw) {
    __shared__ float uf[1024];
    __shared__ int lab[32];
    __shared__ int is64;
    int t = threadIdx.x;   // 1024 threads, one per element of u (32x32)
    uint32_t o0, o1;
    threefry2x32(0u, 42u, 0u, (uint32_t)t, o0, o1);   // counter = (hi=0, lo=n)
    uint32_t bits = o0 ^ o1;                           // partitionable fold
    uf[t] = __uint_as_float((bits >> 9) | 0x3f800000u) - 1.0f;
    if (t == 0) {
        int all0 = 1;
        for (int i = 1; i < 32; i += 2) all0 &= (labels_raw[i] == 0);
        is64 = all0;
    }
    __syncthreads();
    if (t < 32) lab[t] = is64 ? labels_raw[2 * t] : labels_raw[t];
    __syncthreads();
    if (t < 32) {
        int lb = lab[t];
        float best = -2.0f; int bi = 0;
        for (int j = 0; j < 32; j++) {
            float v = (lab[j] != lb) ? uf[t * 32 + j] : -1.0f;
            if (v > best) { best = v; bi = j; }    // first-max ties
        }
        g_negidx[t] = bi;
    }
}

// ---------------- Kernel E: loss terms (warp per (b,i), bf16 inputs) ------
__global__ void loss_kernel() {
    __shared__ float part[8];
    int wid = threadIdx.x >> 5, lane = threadIdx.x & 31;
    int gw = blockIdx.x * 8 + wid;          // 0..32767
    int b = gw >> 10, i = gw & 1023;
    unsigned long long key = g_arg[gw];
    int idx = (int)(0xFFFFFFFFu - (unsigned int)(key & 0xFFFFFFFFull));
    int nb = g_negidx[b];
    // rows of 256 bf16 = 64 uint2 (4 bf16 each); lane handles 2 uint2
    const uint2* q  = (const uint2*)(g_qgt + (size_t)gw * NC);
    const uint2* kp = (const uint2*)(g_kgt + ((size_t)b  * NS + idx) * NC);
    const uint2* kn = (const uint2*)(g_kgt + ((size_t)nb * NS + i)   * NC);
    float dp = 0.f, dn = 0.f;
#pragma unroll
    for (int u = 0; u < 2; u++) {
        int c2 = lane + u * 32;
        uint2 qv = q[c2], pv = kp[c2], nv = kn[c2];
        float2 q0 = __bfloat1622float2(*(const __nv_bfloat162*)&qv.x);
        float2 q1 = __bfloat1622float2(*(const __nv_bfloat162*)&qv.y);
        float2 p0 = __bfloat1622float2(*(const __nv_bfloat162*)&pv.x);
        float2 p1 = __bfloat1622float2(*(const __nv_bfloat162*)&pv.y);
        float2 n0 = __bfloat1622float2(*(const __nv_bfloat162*)&nv.x);
        float2 n1 = __bfloat1622float2(*(const __nv_bfloat162*)&nv.y);
        dp += q0.x * p0.x + q0.y * p0.y + q1.x * p1.x + q1.y * p1.y;
        dn += q0.x * n0.x + q0.y * n0.y + q1.x * n1.x + q1.y * n1.y;
    }
#pragma unroll
    for (int off = 16; off; off >>= 1) {
        dp += __shfl_xor_sync(0xFFFFFFFFu, dp, off);
        dn += __shfl_xor_sync(0xFFFFFFFFu, dn, off);
    }
    if (lane == 0) {
        float p = dp * 10.0f;   // / TEMP
        float n = dn * 10.0f;
        part[wid] = logf(expf(p) + expf(n) + 1e-6f) - p;
    }
    __syncthreads();
    if (threadIdx.x == 0) {
        float s = 0.f;
        for (int w = 0; w < 8; w++) s += part[w];
        atomicAdd(&g_loss, s);
    }
}

__global__ void finalize_kernel(float* out) {
    out[0] = g_loss * (1.0f / 32768.0f);   // mean * LAM(=1)
}

// ---------------- entry ----------------
extern "C" void kernel_launch(void* const* d_in, const int* in_sizes, int n_in,
                              void* d_out, int out_size) {
    const float* q_b    = (const float*)d_in[0];
    const float* k_b    = (const float*)d_in[1];
    const float* q_grid = (const float*)d_in[2];
    const float* k_grid = (const float*)d_in[3];
    const int*   labels = (const int*)d_in[4];

    static int smem_set = 0;
    if (!smem_set) {
        cudaFuncSetAttribute(mma_argmax_kernel,
                             cudaFuncAttributeMaxDynamicSharedMemorySize, SMEM_SZ);
        smem_set = 1;
    }

    prep_kernel<<<dim3(32, 32, 4), 256>>>(q_b, k_b, q_grid, k_grid);
    negidx_kernel<<<1, 1024>>>(labels);
    mma_argmax_kernel<<<dim3(2, 8, 32), 256, SMEM_SZ>>>();
    loss_kernel<<<4096, 256>>>();
    finalize_kernel<<<1, 1>>>((float*)d_out);
}